// round 1
// baseline (speedup 1.0000x reference)
#include <cuda_runtime.h>

#define B_ 8
#define L_ 1024
#define D_ 768
#define H_ 12

// ---------------- scratch (device globals; no allocations allowed) ----------
__device__ float g_q[B_ * L_ * D_];
__device__ float g_k[B_ * L_ * D_];
__device__ float g_v[B_ * L_ * D_];
__device__ float g_n[B_ * L_ * D_];
__device__ float g_tnk[(long)B_ * L_ * L_];
__device__ float g_ink[(long)B_ * L_ * L_];
__device__ float g_enh[(long)B_ * L_ * L_];
__device__ float g_att[B_ * L_ * D_];

// ---------------------------------------------------------------------------
// Generic NT GEMM: C[m,n] = sum_k A[m,k] * B[n,k] (+ bias[n])
// A: [M,K] row-major, B: [N,K] row-major, C: [M,N] row-major.
// 128x128 block tile, BK=8, 256 threads, 8x8 per thread.
// Requires M%128==0, N%128==0, K%8==0 (true for all uses here).
// ---------------------------------------------------------------------------
__global__ void __launch_bounds__(256, 2) gemm_nt(
    const float* __restrict__ A, const float* __restrict__ B,
    float* __restrict__ C, const float* __restrict__ bias,
    int M, int N, int K,
    long sA, long sB, long sC)
{
    __shared__ __align__(16) float As[8][128];
    __shared__ __align__(16) float Bs[8][128];

    A += (long)blockIdx.z * sA;
    B += (long)blockIdx.z * sB;
    C += (long)blockIdx.z * sC;

    const int bm = blockIdx.y * 128;
    const int bn = blockIdx.x * 128;
    const int tid = threadIdx.x;
    const int tx = tid & 15;
    const int ty = tid >> 4;
    const int lrow = tid >> 1;         // 0..127
    const int lcol = (tid & 1) * 4;    // 0 or 4

    const float* Ap = A + (long)(bm + lrow) * K + lcol;
    const float* Bp = B + (long)(bn + lrow) * K + lcol;

    float acc[8][8];
#pragma unroll
    for (int i = 0; i < 8; i++)
#pragma unroll
        for (int j = 0; j < 8; j++) acc[i][j] = 0.f;

    for (int k0 = 0; k0 < K; k0 += 8) {
        float4 av = *(const float4*)(Ap + k0);
        float4 bv = *(const float4*)(Bp + k0);
        __syncthreads();
        As[lcol + 0][lrow] = av.x;
        As[lcol + 1][lrow] = av.y;
        As[lcol + 2][lrow] = av.z;
        As[lcol + 3][lrow] = av.w;
        Bs[lcol + 0][lrow] = bv.x;
        Bs[lcol + 1][lrow] = bv.y;
        Bs[lcol + 2][lrow] = bv.z;
        Bs[lcol + 3][lrow] = bv.w;
        __syncthreads();
#pragma unroll
        for (int kk = 0; kk < 8; kk++) {
            float a[8], b[8];
            float4 t;
            t = *(const float4*)&As[kk][ty * 4];
            a[0] = t.x; a[1] = t.y; a[2] = t.z; a[3] = t.w;
            t = *(const float4*)&As[kk][64 + ty * 4];
            a[4] = t.x; a[5] = t.y; a[6] = t.z; a[7] = t.w;
            t = *(const float4*)&Bs[kk][tx * 4];
            b[0] = t.x; b[1] = t.y; b[2] = t.z; b[3] = t.w;
            t = *(const float4*)&Bs[kk][64 + tx * 4];
            b[4] = t.x; b[5] = t.y; b[6] = t.z; b[7] = t.w;
#pragma unroll
            for (int i = 0; i < 8; i++)
#pragma unroll
                for (int j = 0; j < 8; j++)
                    acc[i][j] = fmaf(a[i], b[j], acc[i][j]);
        }
    }

    float bb[8];
    if (bias) {
#pragma unroll
        for (int j = 0; j < 4; j++) {
            bb[j]     = bias[bn + tx * 4 + j];
            bb[4 + j] = bias[bn + 64 + tx * 4 + j];
        }
    } else {
#pragma unroll
        for (int j = 0; j < 8; j++) bb[j] = 0.f;
    }

#pragma unroll
    for (int half = 0; half < 2; half++) {
#pragma unroll
        for (int r = 0; r < 4; r++) {
            const int row = bm + half * 64 + ty * 4 + r;
            float* cp = C + (long)row * N + bn;
            const int ar = half * 4 + r;
            float4 o0 = make_float4(acc[ar][0] + bb[0], acc[ar][1] + bb[1],
                                    acc[ar][2] + bb[2], acc[ar][3] + bb[3]);
            float4 o1 = make_float4(acc[ar][4] + bb[4], acc[ar][5] + bb[5],
                                    acc[ar][6] + bb[6], acc[ar][7] + bb[7]);
            *(float4*)(cp + tx * 4) = o0;
            *(float4*)(cp + 64 + tx * 4) = o1;
        }
    }
}

// ---------------------------------------------------------------------------
// Fused attention: per (b,h), 64 query rows per block.
//   S = Qh Khᵀ ; S = (S + enh[b]) / 16 ; online softmax ; O = P Vh
// Writes O to g_att[b][l][h*64+d].
// Dynamic smem: sQ[64][64](d-major) + sK[64][64](d-major) + sV[64][64](j-major)
//               + sP[64][68](j-major, padded) = 66560 B.
// ---------------------------------------------------------------------------
__global__ void __launch_bounds__(256) attn_kernel(
    const float* __restrict__ Q, const float* __restrict__ K,
    const float* __restrict__ V, const float* __restrict__ E,
    float* __restrict__ O)
{
    extern __shared__ float sh[];
    float* sQ = sh;             // 4096
    float* sK = sh + 4096;      // 4096
    float* sV = sh + 8192;      // 4096
    float* sP = sh + 12288;     // 64*68

    const int b = blockIdx.y / H_;
    const int h = blockIdx.y % H_;
    const int l0 = blockIdx.x * 64;
    const int tid = threadIdx.x;
    const int tx = tid & 15;
    const int ty = tid >> 4;
    const int i0 = ty * 4;
    const int j0 = tx * 4;

    const float* qb = Q + ((long)b * L_ + l0) * D_ + h * 64;
    const float* kb = K + (long)b * L_ * D_ + h * 64;
    const float* vb = V + (long)b * L_ * D_ + h * 64;
    const float* eb = E + (long)b * L_ * L_ + (long)l0 * L_;

    // load Q tile transposed: sQ[d][i]
#pragma unroll
    for (int it = 0; it < 4; it++) {
        int f = tid + it * 256;
        int i = f >> 4;
        int d = (f & 15) << 2;
        float4 t = *(const float4*)(qb + (long)i * D_ + d);
        sQ[(d + 0) * 64 + i] = t.x;
        sQ[(d + 1) * 64 + i] = t.y;
        sQ[(d + 2) * 64 + i] = t.z;
        sQ[(d + 3) * 64 + i] = t.w;
    }

    float mrow[4], lrow[4], o[4][4];
#pragma unroll
    for (int r = 0; r < 4; r++) {
        mrow[r] = -1e30f;
        lrow[r] = 0.f;
#pragma unroll
        for (int c = 0; c < 4; c++) o[r][c] = 0.f;
    }

    for (int jb = 0; jb < 16; jb++) {
        __syncthreads();  // previous PV reads of sP/sV done; Q visible (iter 0)

        // load K tile transposed: sK[d][j]
#pragma unroll
        for (int it = 0; it < 4; it++) {
            int f = tid + it * 256;
            int j = f >> 4;
            int d = (f & 15) << 2;
            float4 t = *(const float4*)(kb + (long)(jb * 64 + j) * D_ + d);
            sK[(d + 0) * 64 + j] = t.x;
            sK[(d + 1) * 64 + j] = t.y;
            sK[(d + 2) * 64 + j] = t.z;
            sK[(d + 3) * 64 + j] = t.w;
        }
        __syncthreads();

        // prefetch V tile into registers (overlaps with S compute)
        float4 vreg[4];
#pragma unroll
        for (int it = 0; it < 4; it++) {
            int f = tid + it * 256;
            int j = f >> 4;
            int d = (f & 15) << 2;
            vreg[it] = *(const float4*)(vb + (long)(jb * 64 + j) * D_ + d);
        }

        // S = Q Kᵀ (4x4 micro-tile per thread)
        float s[4][4];
#pragma unroll
        for (int r = 0; r < 4; r++)
#pragma unroll
            for (int c = 0; c < 4; c++) s[r][c] = 0.f;
#pragma unroll
        for (int d = 0; d < 64; d++) {
            float4 aq = *(const float4*)(sQ + d * 64 + i0);
            float4 bk = *(const float4*)(sK + d * 64 + j0);
            float a[4] = {aq.x, aq.y, aq.z, aq.w};
            float bv[4] = {bk.x, bk.y, bk.z, bk.w};
#pragma unroll
            for (int r = 0; r < 4; r++)
#pragma unroll
                for (int c = 0; c < 4; c++)
                    s[r][c] = fmaf(a[r], bv[c], s[r][c]);
        }

        // add enhance term, scale by 1/(2*sqrt(64)) = 1/16
#pragma unroll
        for (int r = 0; r < 4; r++) {
            float4 e4 = *(const float4*)(eb + (long)(i0 + r) * L_ + jb * 64 + j0);
            s[r][0] = (s[r][0] + e4.x) * 0.0625f;
            s[r][1] = (s[r][1] + e4.y) * 0.0625f;
            s[r][2] = (s[r][2] + e4.z) * 0.0625f;
            s[r][3] = (s[r][3] + e4.w) * 0.0625f;
        }

        // stage V tile: sV[j][d]
#pragma unroll
        for (int it = 0; it < 4; it++) {
            int f = tid + it * 256;
            int j = f >> 4;
            int d = (f & 15) << 2;
            *(float4*)(sV + j * 64 + d) = vreg[it];
        }

        // online softmax (rows i0..i0+3 live on the 16 lanes sharing ty)
#pragma unroll
        for (int r = 0; r < 4; r++) {
            float mt = fmaxf(fmaxf(s[r][0], s[r][1]), fmaxf(s[r][2], s[r][3]));
#pragma unroll
            for (int off = 8; off > 0; off >>= 1)
                mt = fmaxf(mt, __shfl_xor_sync(0xffffffffu, mt, off));
            float mn = fmaxf(mrow[r], mt);
            float sc = __expf(mrow[r] - mn);
            float rs = 0.f;
#pragma unroll
            for (int c = 0; c < 4; c++) {
                s[r][c] = __expf(s[r][c] - mn);
                rs += s[r][c];
            }
#pragma unroll
            for (int off = 8; off > 0; off >>= 1)
                rs += __shfl_xor_sync(0xffffffffu, rs, off);
            lrow[r] = lrow[r] * sc + rs;
            mrow[r] = mn;
#pragma unroll
            for (int c = 0; c < 4; c++) o[r][c] *= sc;
        }

        // store P transposed: sP[j][i] (float4 across rows)
#pragma unroll
        for (int c = 0; c < 4; c++) {
            float4 pv = make_float4(s[0][c], s[1][c], s[2][c], s[3][c]);
            *(float4*)(sP + (j0 + c) * 68 + i0) = pv;
        }
        __syncthreads();

        // O += P V
#pragma unroll
        for (int j = 0; j < 64; j++) {
            float4 p4 = *(const float4*)(sP + j * 68 + i0);
            float4 v4 = *(const float4*)(sV + j * 64 + j0);
            float p[4] = {p4.x, p4.y, p4.z, p4.w};
            float vv[4] = {v4.x, v4.y, v4.z, v4.w};
#pragma unroll
            for (int r = 0; r < 4; r++)
#pragma unroll
                for (int c = 0; c < 4; c++)
                    o[r][c] = fmaf(p[r], vv[c], o[r][c]);
        }
    }

    // normalize + write to g_att[b][l][h*64+d]
    float* ob = O + ((long)b * L_ + l0) * D_ + h * 64;
#pragma unroll
    for (int r = 0; r < 4; r++) {
        float inv = 1.f / lrow[r];
        float4 w = make_float4(o[r][0] * inv, o[r][1] * inv,
                               o[r][2] * inv, o[r][3] * inv);
        *(float4*)(ob + (long)(i0 + r) * D_ + j0) = w;
    }
}

// ---------------------------------------------------------------------------
extern "C" void kernel_launch(void* const* d_in, const int* in_sizes, int n_in,
                              void* d_out, int out_size)
{
    const float* query = (const float*)d_in[0];
    const float* key   = (const float*)d_in[1];
    const float* value = (const float*)d_in[2];
    const float* news  = (const float*)d_in[3];
    const float* Wq = (const float*)d_in[4];
    const float* bq = (const float*)d_in[5];
    const float* Wk = (const float*)d_in[6];
    const float* bk = (const float*)d_in[7];
    const float* Wv = (const float*)d_in[8];
    const float* bv = (const float*)d_in[9];
    const float* Wn = (const float*)d_in[10];
    const float* bn = (const float*)d_in[11];
    const float* Wo = (const float*)d_in[12];
    const float* bo = (const float*)d_in[13];
    // d_in[14] = pos. Mathematically irrelevant: pos!=0 yields the identical
    // score modifier (swapaxes of the swapped-operand enh == pos==0 enh).

    float *pq, *pk, *pv, *pn, *ptnk, *pink, *penh, *patt;
    cudaGetSymbolAddress((void**)&pq,   g_q);
    cudaGetSymbolAddress((void**)&pk,   g_k);
    cudaGetSymbolAddress((void**)&pv,   g_v);
    cudaGetSymbolAddress((void**)&pn,   g_n);
    cudaGetSymbolAddress((void**)&ptnk, g_tnk);
    cudaGetSymbolAddress((void**)&pink, g_ink);
    cudaGetSymbolAddress((void**)&penh, g_enh);
    cudaGetSymbolAddress((void**)&patt, g_att);

    const int M = B_ * L_;  // 8192
    dim3 blk(256);

    // projections: x @ W^T + b
    gemm_nt<<<dim3(D_ / 128, M / 128, 1), blk>>>(query, Wq, pq, bq, M, D_, D_, 0, 0, 0);
    gemm_nt<<<dim3(D_ / 128, M / 128, 1), blk>>>(key,   Wk, pk, bk, M, D_, D_, 0, 0, 0);
    gemm_nt<<<dim3(D_ / 128, M / 128, 1), blk>>>(value, Wv, pv, bv, M, D_, D_, 0, 0, 0);
    gemm_nt<<<dim3(D_ / 128, M / 128, 1), blk>>>(news,  Wn, pn, bn, M, D_, D_, 0, 0, 0);

    // t_nk = q @ nk^T, i_nk = k @ nk^T (batched over B)
    gemm_nt<<<dim3(L_ / 128, L_ / 128, B_), blk>>>(pq, pn, ptnk, nullptr,
        L_, L_, D_, (long)L_ * D_, (long)L_ * D_, (long)L_ * L_);
    gemm_nt<<<dim3(L_ / 128, L_ / 128, B_), blk>>>(pk, pn, pink, nullptr,
        L_, L_, D_, (long)L_ * D_, (long)L_ * D_, (long)L_ * L_);

    // enh = t_nk @ i_nk^T (batched)
    gemm_nt<<<dim3(L_ / 128, L_ / 128, B_), blk>>>(ptnk, pink, penh, nullptr,
        L_, L_, L_, (long)L_ * L_, (long)L_ * L_, (long)L_ * L_);

    // fused attention (QK^T + enh + softmax + PV)
    const int attn_smem = (12288 + 64 * 68) * 4;  // 66560 B
    cudaFuncSetAttribute(attn_kernel, cudaFuncAttributeMaxDynamicSharedMemorySize,
                         attn_smem);
    attn_kernel<<<dim3(L_ / 64, B_ * H_), blk, attn_smem>>>(pq, pk, pv, penh, patt);

    // output projection -> d_out
    gemm_nt<<<dim3(D_ / 128, M / 128, 1), blk>>>(patt, Wo, (float*)d_out, bo,
                                                 M, D_, D_, 0, 0, 0);
}

// round 3
// speedup vs baseline: 1.2592x; 1.2592x over previous
#include <cuda_runtime.h>
#include <stdint.h>

#define B_ 8
#define L_ 1024
#define D_ 768
#define H_ 12

// ---------------- scratch (device globals; no allocations allowed) ----------
__device__ float g_q[B_ * L_ * D_];
__device__ float g_k[B_ * L_ * D_];
__device__ float g_v[B_ * L_ * D_];
__device__ float g_n[B_ * L_ * D_];
__device__ float g_tnk[(long)B_ * L_ * L_];
__device__ float g_ink[(long)B_ * L_ * L_];
__device__ float g_enh[(long)B_ * L_ * L_];
__device__ float g_att[B_ * L_ * D_];

// ---------------- helpers ----------------------------------------------------
__device__ __forceinline__ uint32_t smem_u32(const void* p) {
    uint32_t a;
    asm("{ .reg .u64 t; cvta.to.shared.u64 t, %1; cvt.u32.u64 %0, t; }"
        : "=r"(a) : "l"(p));
    return a;
}
__device__ __forceinline__ uint32_t f2tf32(float x) {
    uint32_t r;
    asm("cvt.rna.tf32.f32 %0, %1;" : "=r"(r) : "f"(x));
    return r;
}
__device__ __forceinline__ void split4(float4 a, uint4& h, uint4& l) {
    h.x = f2tf32(a.x); l.x = f2tf32(a.x - __uint_as_float(h.x));
    h.y = f2tf32(a.y); l.y = f2tf32(a.y - __uint_as_float(h.y));
    h.z = f2tf32(a.z); l.z = f2tf32(a.z - __uint_as_float(h.z));
    h.w = f2tf32(a.w); l.w = f2tf32(a.w - __uint_as_float(h.w));
}
__device__ __forceinline__ void ldsm4(uint32_t* r, uint32_t addr) {
    asm volatile("ldmatrix.sync.aligned.m8n8.x4.shared.b16 {%0,%1,%2,%3}, [%4];"
                 : "=r"(r[0]), "=r"(r[1]), "=r"(r[2]), "=r"(r[3]) : "r"(addr));
}
__device__ __forceinline__ void mma8(float* d, const uint32_t* a, const uint32_t* b) {
    asm volatile(
        "mma.sync.aligned.m16n8k8.row.col.f32.tf32.tf32.f32 "
        "{%0,%1,%2,%3}, {%4,%5,%6,%7}, {%8,%9}, {%0,%1,%2,%3};"
        : "+f"(d[0]), "+f"(d[1]), "+f"(d[2]), "+f"(d[3])
        : "r"(a[0]), "r"(a[1]), "r"(a[2]), "r"(a[3]), "r"(b[0]), "r"(b[1]));
}

// ---------------------------------------------------------------------------
// 3x-tf32 error-compensated NT GEMM via mma.sync:
//   C[m,n] = sum_k A[m,k]*B[n,k] (+bias[n]), fp32 in/out, ~fp32 accuracy.
// CTA 128x128, K-chunk 32, 8 warps (2x4), warp tile 64x32.
// smem: Ah/Al/Bh/Bl each [128][36] floats (pad 4) = 73728 B total.
// Requires M%128==0, N%128==0, K%32==0.
// ---------------------------------------------------------------------------
__global__ void __launch_bounds__(256, 2) tc_gemm(
    const float* __restrict__ A, const float* __restrict__ B,
    float* __restrict__ C, const float* __restrict__ bias,
    int M, int N, int K, long sA, long sB, long sC)
{
    extern __shared__ float sm[];
    float* sAh = sm;                 // 128*36
    float* sAl = sAh + 4608;
    float* sBh = sAl + 4608;
    float* sBl = sBh + 4608;

    const int tid = threadIdx.x;
    const int lane = tid & 31;
    const int warp = tid >> 5;
    const int wm = warp >> 2;        // 0..1
    const int wn = warp & 3;         // 0..3
    const int bm = blockIdx.y * 128;
    const int bn = blockIdx.x * 128;
    A += (long)blockIdx.z * sA;
    B += (long)blockIdx.z * sB;
    C += (long)blockIdx.z * sC;

    // global-load mapping: 32 rows x 8 float4-cols per matrix, 4 iters
    const int row0 = tid >> 3;          // 0..31
    const int c4 = (tid & 7) << 2;      // 0,4,...,28
    const float* Ap = A + (long)(bm + row0) * K + c4;
    const float* Bp = B + (long)(bn + row0) * K + c4;

    // ldmatrix base byte-addresses
    const uint32_t aOff =
        (((uint32_t)(wm * 64 + (lane & 15)) * 36u) + ((lane & 16) >> 2)) << 2;
    const uint32_t bOff =
        (((uint32_t)(wn * 32 + (lane & 7) + ((lane & 16) >> 1)) * 36u) +
         ((lane & 8) >> 1)) << 2;
    const uint32_t aH = smem_u32(sAh) + aOff;
    const uint32_t aL = smem_u32(sAl) + aOff;
    const uint32_t bH = smem_u32(sBh) + bOff;
    const uint32_t bL = smem_u32(sBl) + bOff;

    float acc[4][4][4];
#pragma unroll
    for (int m = 0; m < 4; m++)
#pragma unroll
        for (int n = 0; n < 4; n++)
#pragma unroll
            for (int r = 0; r < 4; r++) acc[m][n][r] = 0.f;

    const int NC = K >> 5;
    for (int c = 0; c < NC; c++) {
        const int k0 = c << 5;
        float4 av[4], bv[4];
#pragma unroll
        for (int it = 0; it < 4; it++) {
            av[it] = *(const float4*)(Ap + (long)(it * 32) * K + k0);
            bv[it] = *(const float4*)(Bp + (long)(it * 32) * K + k0);
        }
        __syncthreads();  // previous chunk's LDSM done
#pragma unroll
        for (int it = 0; it < 4; it++) {
            const int idx = (row0 + it * 32) * 36 + c4;
            uint4 h, l;
            split4(av[it], h, l);
            *(uint4*)(sAh + idx) = h;
            *(uint4*)(sAl + idx) = l;
            split4(bv[it], h, l);
            *(uint4*)(sBh + idx) = h;
            *(uint4*)(sBl + idx) = l;
        }
        __syncthreads();

#pragma unroll
        for (int s = 0; s < 4; s++) {
            const uint32_t ks = (uint32_t)(s * 8) << 2;  // byte offset in row
            uint32_t bh[8], bl[8];
            ldsm4(bh + 0, bH + ks);
            ldsm4(bh + 4, bH + ks + (16 * 36 << 2));
            ldsm4(bl + 0, bL + ks);
            ldsm4(bl + 4, bL + ks + (16 * 36 << 2));
            uint32_t af[16];
#pragma unroll
            for (int m = 0; m < 4; m++)
                ldsm4(af + 4 * m, aH + ks + ((uint32_t)(m * 16 * 36) << 2));
#pragma unroll
            for (int m = 0; m < 4; m++)
#pragma unroll
                for (int n = 0; n < 4; n++) {
                    mma8(acc[m][n], af + 4 * m, bh + 2 * n);
                    mma8(acc[m][n], af + 4 * m, bl + 2 * n);
                }
#pragma unroll
            for (int m = 0; m < 4; m++)
                ldsm4(af + 4 * m, aL + ks + ((uint32_t)(m * 16 * 36) << 2));
#pragma unroll
            for (int m = 0; m < 4; m++)
#pragma unroll
                for (int n = 0; n < 4; n++)
                    mma8(acc[m][n], af + 4 * m, bh + 2 * n);
        }
    }

    // epilogue: direct register -> gmem (float2 stores), optional bias
    const int g = lane >> 2;
    const int t = lane & 3;
#pragma unroll
    for (int n = 0; n < 4; n++) {
        const int col = bn + wn * 32 + n * 8 + t * 2;
        float b0 = 0.f, b1 = 0.f;
        if (bias) { b0 = bias[col]; b1 = bias[col + 1]; }
#pragma unroll
        for (int m = 0; m < 4; m++) {
            const int r0 = bm + wm * 64 + m * 16 + g;
            float2 v0 = make_float2(acc[m][n][0] + b0, acc[m][n][1] + b1);
            float2 v1 = make_float2(acc[m][n][2] + b0, acc[m][n][3] + b1);
            *(float2*)(C + (long)r0 * N + col) = v0;
            *(float2*)(C + (long)(r0 + 8) * N + col) = v1;
        }
    }
}

// ---------------------------------------------------------------------------
// Fused attention (unchanged): per (b,h), 64 query rows per block.
// ---------------------------------------------------------------------------
__global__ void __launch_bounds__(256) attn_kernel(
    const float* __restrict__ Q, const float* __restrict__ K,
    const float* __restrict__ V, const float* __restrict__ E,
    float* __restrict__ O)
{
    extern __shared__ float sh[];
    float* sQ = sh;
    float* sK = sh + 4096;
    float* sV = sh + 8192;
    float* sP = sh + 12288;

    const int b = blockIdx.y / H_;
    const int h = blockIdx.y % H_;
    const int l0 = blockIdx.x * 64;
    const int tid = threadIdx.x;
    const int tx = tid & 15;
    const int ty = tid >> 4;
    const int i0 = ty * 4;
    const int j0 = tx * 4;

    const float* qb = Q + ((long)b * L_ + l0) * D_ + h * 64;
    const float* kb = K + (long)b * L_ * D_ + h * 64;
    const float* vb = V + (long)b * L_ * D_ + h * 64;
    const float* eb = E + (long)b * L_ * L_ + (long)l0 * L_;

#pragma unroll
    for (int it = 0; it < 4; it++) {
        int f = tid + it * 256;
        int i = f >> 4;
        int d = (f & 15) << 2;
        float4 t = *(const float4*)(qb + (long)i * D_ + d);
        sQ[(d + 0) * 64 + i] = t.x;
        sQ[(d + 1) * 64 + i] = t.y;
        sQ[(d + 2) * 64 + i] = t.z;
        sQ[(d + 3) * 64 + i] = t.w;
    }

    float mrow[4], lrow[4], o[4][4];
#pragma unroll
    for (int r = 0; r < 4; r++) {
        mrow[r] = -1e30f;
        lrow[r] = 0.f;
#pragma unroll
        for (int c = 0; c < 4; c++) o[r][c] = 0.f;
    }

    for (int jb = 0; jb < 16; jb++) {
        __syncthreads();
#pragma unroll
        for (int it = 0; it < 4; it++) {
            int f = tid + it * 256;
            int j = f >> 4;
            int d = (f & 15) << 2;
            float4 t = *(const float4*)(kb + (long)(jb * 64 + j) * D_ + d);
            sK[(d + 0) * 64 + j] = t.x;
            sK[(d + 1) * 64 + j] = t.y;
            sK[(d + 2) * 64 + j] = t.z;
            sK[(d + 3) * 64 + j] = t.w;
        }
        __syncthreads();

        float4 vreg[4];
#pragma unroll
        for (int it = 0; it < 4; it++) {
            int f = tid + it * 256;
            int j = f >> 4;
            int d = (f & 15) << 2;
            vreg[it] = *(const float4*)(vb + (long)(jb * 64 + j) * D_ + d);
        }

        float s[4][4];
#pragma unroll
        for (int r = 0; r < 4; r++)
#pragma unroll
            for (int c = 0; c < 4; c++) s[r][c] = 0.f;
#pragma unroll
        for (int d = 0; d < 64; d++) {
            float4 aq = *(const float4*)(sQ + d * 64 + i0);
            float4 bk = *(const float4*)(sK + d * 64 + j0);
            float a[4] = {aq.x, aq.y, aq.z, aq.w};
            float bb2[4] = {bk.x, bk.y, bk.z, bk.w};
#pragma unroll
            for (int r = 0; r < 4; r++)
#pragma unroll
                for (int c = 0; c < 4; c++)
                    s[r][c] = fmaf(a[r], bb2[c], s[r][c]);
        }

#pragma unroll
        for (int r = 0; r < 4; r++) {
            float4 e4 = *(const float4*)(eb + (long)(i0 + r) * L_ + jb * 64 + j0);
            s[r][0] = (s[r][0] + e4.x) * 0.0625f;
            s[r][1] = (s[r][1] + e4.y) * 0.0625f;
            s[r][2] = (s[r][2] + e4.z) * 0.0625f;
            s[r][3] = (s[r][3] + e4.w) * 0.0625f;
        }

#pragma unroll
        for (int it = 0; it < 4; it++) {
            int f = tid + it * 256;
            int j = f >> 4;
            int d = (f & 15) << 2;
            *(float4*)(sV + j * 64 + d) = vreg[it];
        }

#pragma unroll
        for (int r = 0; r < 4; r++) {
            float mt = fmaxf(fmaxf(s[r][0], s[r][1]), fmaxf(s[r][2], s[r][3]));
#pragma unroll
            for (int off = 8; off > 0; off >>= 1)
                mt = fmaxf(mt, __shfl_xor_sync(0xffffffffu, mt, off));
            float mn = fmaxf(mrow[r], mt);
            float sc = __expf(mrow[r] - mn);
            float rs = 0.f;
#pragma unroll
            for (int c = 0; c < 4; c++) {
                s[r][c] = __expf(s[r][c] - mn);
                rs += s[r][c];
            }
#pragma unroll
            for (int off = 8; off > 0; off >>= 1)
                rs += __shfl_xor_sync(0xffffffffu, rs, off);
            lrow[r] = lrow[r] * sc + rs;
            mrow[r] = mn;
#pragma unroll
            for (int c = 0; c < 4; c++) o[r][c] *= sc;
        }

#pragma unroll
        for (int c = 0; c < 4; c++) {
            float4 pv = make_float4(s[0][c], s[1][c], s[2][c], s[3][c]);
            *(float4*)(sP + (j0 + c) * 68 + i0) = pv;
        }
        __syncthreads();

#pragma unroll
        for (int j = 0; j < 64; j++) {
            float4 p4 = *(const float4*)(sP + j * 68 + i0);
            float4 v4 = *(const float4*)(sV + j * 64 + j0);
            float p[4] = {p4.x, p4.y, p4.z, p4.w};
            float vv[4] = {v4.x, v4.y, v4.z, v4.w};
#pragma unroll
            for (int r = 0; r < 4; r++)
#pragma unroll
                for (int c = 0; c < 4; c++)
                    o[r][c] = fmaf(p[r], vv[c], o[r][c]);
        }
    }

    float* ob = O + ((long)b * L_ + l0) * D_ + h * 64;
#pragma unroll
    for (int r = 0; r < 4; r++) {
        float inv = 1.f / lrow[r];
        float4 w = make_float4(o[r][0] * inv, o[r][1] * inv,
                               o[r][2] * inv, o[r][3] * inv);
        *(float4*)(ob + (long)(i0 + r) * D_ + j0) = w;
    }
}

// ---------------------------------------------------------------------------
extern "C" void kernel_launch(void* const* d_in, const int* in_sizes, int n_in,
                              void* d_out, int out_size)
{
    const float* query = (const float*)d_in[0];
    const float* key   = (const float*)d_in[1];
    const float* value = (const float*)d_in[2];
    const float* news  = (const float*)d_in[3];
    const float* Wq = (const float*)d_in[4];
    const float* bq = (const float*)d_in[5];
    const float* Wk = (const float*)d_in[6];
    const float* bk = (const float*)d_in[7];
    const float* Wv = (const float*)d_in[8];
    const float* bv = (const float*)d_in[9];
    const float* Wn = (const float*)d_in[10];
    const float* bn = (const float*)d_in[11];
    const float* Wo = (const float*)d_in[12];
    const float* bo = (const float*)d_in[13];
    // d_in[14] = pos. Mathematically irrelevant (swapaxes of swapped enh == enh).

    float *pq, *pk, *pv, *pn, *ptnk, *pink, *penh, *patt;
    cudaGetSymbolAddress((void**)&pq,   g_q);
    cudaGetSymbolAddress((void**)&pk,   g_k);
    cudaGetSymbolAddress((void**)&pv,   g_v);
    cudaGetSymbolAddress((void**)&pn,   g_n);
    cudaGetSymbolAddress((void**)&ptnk, g_tnk);
    cudaGetSymbolAddress((void**)&pink, g_ink);
    cudaGetSymbolAddress((void**)&penh, g_enh);
    cudaGetSymbolAddress((void**)&patt, g_att);

    const int M = B_ * L_;  // 8192
    dim3 blk(256);
    const int gsmem = 4 * 4608 * 4;  // 73728
    cudaFuncSetAttribute(tc_gemm, cudaFuncAttributeMaxDynamicSharedMemorySize, gsmem);

    // projections: x @ W^T + b
    tc_gemm<<<dim3(D_ / 128, M / 128, 1), blk, gsmem>>>(query, Wq, pq, bq, M, D_, D_, 0, 0, 0);
    tc_gemm<<<dim3(D_ / 128, M / 128, 1), blk, gsmem>>>(key,   Wk, pk, bk, M, D_, D_, 0, 0, 0);
    tc_gemm<<<dim3(D_ / 128, M / 128, 1), blk, gsmem>>>(value, Wv, pv, bv, M, D_, D_, 0, 0, 0);
    tc_gemm<<<dim3(D_ / 128, M / 128, 1), blk, gsmem>>>(news,  Wn, pn, bn, M, D_, D_, 0, 0, 0);

    // t_nk = q @ nk^T, i_nk = k @ nk^T (batched over B)
    tc_gemm<<<dim3(L_ / 128, L_ / 128, B_), blk, gsmem>>>(pq, pn, ptnk, nullptr,
        L_, L_, D_, (long)L_ * D_, (long)L_ * D_, (long)L_ * L_);
    tc_gemm<<<dim3(L_ / 128, L_ / 128, B_), blk, gsmem>>>(pk, pn, pink, nullptr,
        L_, L_, D_, (long)L_ * D_, (long)L_ * D_, (long)L_ * L_);

    // enh = t_nk @ i_nk^T (batched)
    tc_gemm<<<dim3(L_ / 128, L_ / 128, B_), blk, gsmem>>>(ptnk, pink, penh, nullptr,
        L_, L_, L_, (long)L_ * L_, (long)L_ * L_, (long)L_ * L_);

    // fused attention (QK^T + enh + softmax + PV)
    const int attn_smem = (12288 + 64 * 68) * 4;  // 66560 B
    cudaFuncSetAttribute(attn_kernel, cudaFuncAttributeMaxDynamicSharedMemorySize,
                         attn_smem);
    attn_kernel<<<dim3(L_ / 64, B_ * H_), blk, attn_smem>>>(pq, pk, pv, penh, patt);

    // output projection -> d_out
    tc_gemm<<<dim3(D_ / 128, M / 128, 1), blk, gsmem>>>(patt, Wo, (float*)d_out, bo,
                                                        M, D_, D_, 0, 0, 0);
}

// round 4
// speedup vs baseline: 1.5431x; 1.2255x over previous
#include <cuda_runtime.h>
#include <stdint.h>

#define B_ 8
#define L_ 1024
#define D_ 768
#define H_ 12

// ---------------- scratch (device globals; no allocations allowed) ----------
__device__ float g_q[B_ * L_ * D_];
__device__ float g_k[B_ * L_ * D_];
__device__ float g_v[B_ * L_ * D_];
__device__ float g_n[B_ * L_ * D_];
__device__ float g_tnk[(long)B_ * L_ * L_];
__device__ float g_ink[(long)B_ * L_ * L_];
__device__ float g_enh[(long)B_ * L_ * L_];
__device__ float g_att[B_ * L_ * D_];

// ---------------- helpers ----------------------------------------------------
__device__ __forceinline__ uint32_t smem_u32(const void* p) {
    uint32_t a;
    asm("{ .reg .u64 t; cvta.to.shared.u64 t, %1; cvt.u32.u64 %0, t; }"
        : "=r"(a) : "l"(p));
    return a;
}
__device__ __forceinline__ uint32_t f2tf32(float x) {
    uint32_t r;
    asm("cvt.rna.tf32.f32 %0, %1;" : "=r"(r) : "f"(x));
    return r;
}
__device__ __forceinline__ void split4(float4 a, uint4& h, uint4& l) {
    h.x = f2tf32(a.x); l.x = f2tf32(a.x - __uint_as_float(h.x));
    h.y = f2tf32(a.y); l.y = f2tf32(a.y - __uint_as_float(h.y));
    h.z = f2tf32(a.z); l.z = f2tf32(a.z - __uint_as_float(h.z));
    h.w = f2tf32(a.w); l.w = f2tf32(a.w - __uint_as_float(h.w));
}
__device__ __forceinline__ void ldsm4(uint32_t* r, uint32_t addr) {
    asm volatile("ldmatrix.sync.aligned.m8n8.x4.shared.b16 {%0,%1,%2,%3}, [%4];"
                 : "=r"(r[0]), "=r"(r[1]), "=r"(r[2]), "=r"(r[3]) : "r"(addr));
}
__device__ __forceinline__ void mma8(float* d, const uint32_t* a, const uint32_t* b) {
    asm volatile(
        "mma.sync.aligned.m16n8k8.row.col.f32.tf32.tf32.f32 "
        "{%0,%1,%2,%3}, {%4,%5,%6,%7}, {%8,%9}, {%0,%1,%2,%3};"
        : "+f"(d[0]), "+f"(d[1]), "+f"(d[2]), "+f"(d[3])
        : "r"(a[0]), "r"(a[1]), "r"(a[2]), "r"(a[3]), "r"(b[0]), "r"(b[1]));
}

// ---------------------------------------------------------------------------
// 3x-tf32 error-compensated NT GEMM via mma.sync, 2-stage double buffer.
//   C[m,n] = sum_k A[m,k]*B[n,k] (+bias[n]).
// CTA 128x128, K-chunk 32, 8 warps (2x4), warp tile 64x32.
// smem: 2 stages x (Ah/Al/Bh/Bl each [128][36]) = 147456 B -> 1 CTA/SM.
// ---------------------------------------------------------------------------
#define STG_F 18432  // floats per stage (4 * 4608)

__global__ void __launch_bounds__(256) tc_gemm(
    const float* __restrict__ A, const float* __restrict__ B,
    float* __restrict__ C, const float* __restrict__ bias,
    int M, int N, int K, long sA, long sB, long sC)
{
    extern __shared__ float sm[];
    const uint32_t smb = smem_u32(sm);

    const int tid = threadIdx.x;
    const int lane = tid & 31;
    const int warp = tid >> 5;
    const int wm = warp >> 2;
    const int wn = warp & 3;
    const int bm = blockIdx.y * 128;
    const int bn = blockIdx.x * 128;
    A += (long)blockIdx.z * sA;
    B += (long)blockIdx.z * sB;
    C += (long)blockIdx.z * sC;

    const int row0 = tid >> 3;
    const int c4 = (tid & 7) << 2;
    const float* Ap = A + (long)(bm + row0) * K + c4;
    const float* Bp = B + (long)(bn + row0) * K + c4;

    // ldmatrix byte offsets within a stage
    const uint32_t aOff =
        ((((uint32_t)(wm * 64 + (lane & 15)) * 36u) + ((lane & 16) >> 2)) << 2);
    const uint32_t bOff =
        ((((uint32_t)(wn * 32 + (lane & 7) + ((lane & 16) >> 1)) * 36u) +
          ((lane & 8) >> 1)) << 2) + (2 * 4608 << 2);  // sBh array offset

    float acc[4][4][4];
#pragma unroll
    for (int m = 0; m < 4; m++)
#pragma unroll
        for (int n = 0; n < 4; n++)
#pragma unroll
            for (int r = 0; r < 4; r++) acc[m][n][r] = 0.f;

    const int NC = K >> 5;

    // ---- prologue: chunk 0 -> stage 0
    {
        float4 av[4], bv[4];
#pragma unroll
        for (int it = 0; it < 4; it++) {
            av[it] = *(const float4*)(Ap + (long)(it * 32) * K);
            bv[it] = *(const float4*)(Bp + (long)(it * 32) * K);
        }
        float* sAh = sm;
        float* sAl = sm + 4608;
        float* sBh = sm + 9216;
        float* sBl = sm + 13824;
#pragma unroll
        for (int it = 0; it < 4; it++) {
            const int idx = (row0 + it * 32) * 36 + c4;
            uint4 h, l;
            split4(av[it], h, l);
            *(uint4*)(sAh + idx) = h;
            *(uint4*)(sAl + idx) = l;
            split4(bv[it], h, l);
            *(uint4*)(sBh + idx) = h;
            *(uint4*)(sBl + idx) = l;
        }
    }
    __syncthreads();

    for (int c = 0; c < NC; c++) {
        const int buf = c & 1;
        float4 av[4], bv[4];
        if (c + 1 < NC) {
            const int k0 = (c + 1) << 5;
#pragma unroll
            for (int it = 0; it < 4; it++) {
                av[it] = *(const float4*)(Ap + (long)(it * 32) * K + k0);
                bv[it] = *(const float4*)(Bp + (long)(it * 32) * K + k0);
            }
        }

        // MMA phase on stage `buf`
        const uint32_t stB = smb + (uint32_t)buf * (STG_F << 2);
        const uint32_t aH = stB + aOff;
        const uint32_t aL = aH + (4608u << 2);
        const uint32_t bH = stB + bOff;
        const uint32_t bL = bH + (4608u << 2);
#pragma unroll
        for (int s = 0; s < 4; s++) {
            const uint32_t ks = (uint32_t)(s * 8) << 2;
            uint32_t bh[8], bl[8];
            ldsm4(bh + 0, bH + ks);
            ldsm4(bh + 4, bH + ks + (16 * 36 << 2));
            ldsm4(bl + 0, bL + ks);
            ldsm4(bl + 4, bL + ks + (16 * 36 << 2));
            uint32_t af[16];
#pragma unroll
            for (int m = 0; m < 4; m++)
                ldsm4(af + 4 * m, aH + ks + ((uint32_t)(m * 16 * 36) << 2));
#pragma unroll
            for (int m = 0; m < 4; m++)
#pragma unroll
                for (int n = 0; n < 4; n++) {
                    mma8(acc[m][n], af + 4 * m, bh + 2 * n);
                    mma8(acc[m][n], af + 4 * m, bl + 2 * n);
                }
#pragma unroll
            for (int m = 0; m < 4; m++)
                ldsm4(af + 4 * m, aL + ks + ((uint32_t)(m * 16 * 36) << 2));
#pragma unroll
            for (int m = 0; m < 4; m++)
#pragma unroll
                for (int n = 0; n < 4; n++)
                    mma8(acc[m][n], af + 4 * m, bh + 2 * n);
        }

        // split + STS chunk c+1 into stage buf^1
        if (c + 1 < NC) {
            float* st = sm + (buf ^ 1) * STG_F;
            float* sAh = st;
            float* sAl = st + 4608;
            float* sBh = st + 9216;
            float* sBl = st + 13824;
#pragma unroll
            for (int it = 0; it < 4; it++) {
                const int idx = (row0 + it * 32) * 36 + c4;
                uint4 h, l;
                split4(av[it], h, l);
                *(uint4*)(sAh + idx) = h;
                *(uint4*)(sAl + idx) = l;
                split4(bv[it], h, l);
                *(uint4*)(sBh + idx) = h;
                *(uint4*)(sBl + idx) = l;
            }
        }
        __syncthreads();
    }

    // epilogue: registers -> gmem
    const int g = lane >> 2;
    const int t = lane & 3;
#pragma unroll
    for (int n = 0; n < 4; n++) {
        const int col = bn + wn * 32 + n * 8 + t * 2;
        float b0 = 0.f, b1 = 0.f;
        if (bias) { b0 = bias[col]; b1 = bias[col + 1]; }
#pragma unroll
        for (int m = 0; m < 4; m++) {
            const int r0 = bm + wm * 64 + m * 16 + g;
            float2 v0 = make_float2(acc[m][n][0] + b0, acc[m][n][1] + b1);
            float2 v1 = make_float2(acc[m][n][2] + b0, acc[m][n][3] + b1);
            *(float2*)(C + (long)r0 * N + col) = v0;
            *(float2*)(C + (long)(r0 + 8) * N + col) = v1;
        }
    }
}

// ---------------------------------------------------------------------------
// Fused attention via mma.sync.
// Block = 128 q-rows x (b,h). 8 warps, warp w owns rows w*16..w*16+15 (full
// 64 key-cols per warp -> no cross-warp reductions).
//   S = QK^T (1x tf32) ; S = (S+E)/16 ; online softmax ; O = P V (3x tf32).
// P converted acc-layout -> A-layout via quad shuffles (no smem staging).
// smem: sQ[128][68] tf32-hi, sK[64][68] tf32-hi, sVt hi/lo [64][68] (d-major)
//       = 87040 B -> 2 CTAs/SM.
// ---------------------------------------------------------------------------
__global__ void __launch_bounds__(256, 2) attn_mma(
    const float* __restrict__ Q, const float* __restrict__ K,
    const float* __restrict__ V, const float* __restrict__ E,
    float* __restrict__ O)
{
    extern __shared__ float sh[];
    float* sQ = sh;                    // 128*68
    float* sK = sh + 128 * 68;         // 64*68
    float* sVh = sK + 64 * 68;         // [d][key]
    float* sVl = sVh + 64 * 68;

    const int b = blockIdx.y / H_;
    const int h = blockIdx.y % H_;
    const int l0 = blockIdx.x * 128;
    const int tid = threadIdx.x;
    const int lane = tid & 31;
    const int w = tid >> 5;
    const int g = lane >> 2;
    const int t = lane & 3;

    const float* qb = Q + ((long)b * L_ + l0) * D_ + h * 64;
    const float* kb = K + (long)b * L_ * D_ + h * 64;
    const float* vb = V + (long)b * L_ * D_ + h * 64;
    const float* e0 = E + ((long)b * L_ + l0 + w * 16 + g) * L_;
    const float* e1 = e0 + 8 * L_;

    // stage Q (tf32 hi)
#pragma unroll
    for (int it = 0; it < 8; it++) {
        int f = tid + it * 256;
        int row = f >> 4;
        int d4 = (f & 15) << 2;
        float4 v = *(const float4*)(qb + (long)row * D_ + d4);
        uint4 hv;
        hv.x = f2tf32(v.x); hv.y = f2tf32(v.y);
        hv.z = f2tf32(v.z); hv.w = f2tf32(v.w);
        *(uint4*)(sQ + row * 68 + d4) = hv;
    }

    // ldmatrix base addresses
    const uint32_t sQa = smem_u32(sQ) +
        ((((uint32_t)(w * 16 + (lane & 15)) * 68u) + ((lane & 16) >> 2)) << 2);
    const uint32_t bPat =
        ((((uint32_t)((lane & 7) + ((lane & 16) >> 1)) * 68u) +
          ((lane & 8) >> 1)) << 2);
    const uint32_t sKa = smem_u32(sK) + bPat;
    const uint32_t sVha = smem_u32(sVh) + bPat;
    const uint32_t sVla = smem_u32(sVl) + bPat;
    const uint32_t R16 = (16 * 68) << 2;  // 16-row byte stride

    float o[8][4];
#pragma unroll
    for (int j = 0; j < 8; j++)
#pragma unroll
        for (int r = 0; r < 4; r++) o[j][r] = 0.f;
    float m0 = -1e30f, m1 = -1e30f, sum0 = 0.f, sum1 = 0.f;

    for (int jb = 0; jb < 16; jb++) {
        __syncthreads();  // previous iter's LDSM done
        // K tile -> sK (tf32 hi), [key][d]
#pragma unroll
        for (int it = 0; it < 4; it++) {
            int f = tid + it * 256;
            int key = f >> 4;
            int d4 = (f & 15) << 2;
            float4 v = *(const float4*)(kb + (long)(jb * 64 + key) * D_ + d4);
            uint4 hv;
            hv.x = f2tf32(v.x); hv.y = f2tf32(v.y);
            hv.z = f2tf32(v.z); hv.w = f2tf32(v.w);
            *(uint4*)(sK + key * 68 + d4) = hv;
        }
        // V tile -> sVt hi/lo transposed [d][key]
#pragma unroll
        for (int it = 0; it < 4; it++) {
            int f = tid + it * 256;
            int key = f >> 4;
            int d4 = (f & 15) << 2;
            float4 v = *(const float4*)(vb + (long)(jb * 64 + key) * D_ + d4);
            float vv[4] = {v.x, v.y, v.z, v.w};
#pragma unroll
            for (int i = 0; i < 4; i++) {
                uint32_t hi = f2tf32(vv[i]);
                uint32_t lo = f2tf32(vv[i] - __uint_as_float(hi));
                *(uint32_t*)(sVh + (d4 + i) * 68 + key) = hi;
                *(uint32_t*)(sVl + (d4 + i) * 68 + key) = lo;
            }
        }
        __syncthreads();

        // S = Q K^T
        float accS[8][4];
#pragma unroll
        for (int j = 0; j < 8; j++)
#pragma unroll
            for (int r = 0; r < 4; r++) accS[j][r] = 0.f;
#pragma unroll
        for (int s = 0; s < 8; s++) {
            const uint32_t ks = (uint32_t)s * 32;
            uint32_t af[4], bf[16];
            ldsm4(af, sQa + ks);
            ldsm4(bf + 0,  sKa + ks);
            ldsm4(bf + 4,  sKa + ks + R16);
            ldsm4(bf + 8,  sKa + ks + 2 * R16);
            ldsm4(bf + 12, sKa + ks + 3 * R16);
#pragma unroll
            for (int j = 0; j < 8; j++) mma8(accS[j], af, bf + 2 * j);
        }

        // add E, scale by 1/16
#pragma unroll
        for (int j = 0; j < 8; j++) {
            const int col = jb * 64 + 8 * j + 2 * t;
            float2 ea = *(const float2*)(e0 + col);
            float2 ebv = *(const float2*)(e1 + col);
            accS[j][0] = (accS[j][0] + ea.x) * 0.0625f;
            accS[j][1] = (accS[j][1] + ea.y) * 0.0625f;
            accS[j][2] = (accS[j][2] + ebv.x) * 0.0625f;
            accS[j][3] = (accS[j][3] + ebv.y) * 0.0625f;
        }

        // online softmax (rows g / g+8; cols spread over quad lanes)
        float mx0 = -1e30f, mx1 = -1e30f;
#pragma unroll
        for (int j = 0; j < 8; j++) {
            mx0 = fmaxf(mx0, fmaxf(accS[j][0], accS[j][1]));
            mx1 = fmaxf(mx1, fmaxf(accS[j][2], accS[j][3]));
        }
#pragma unroll
        for (int off = 1; off <= 2; off <<= 1) {
            mx0 = fmaxf(mx0, __shfl_xor_sync(0xffffffffu, mx0, off));
            mx1 = fmaxf(mx1, __shfl_xor_sync(0xffffffffu, mx1, off));
        }
        const float nm0 = fmaxf(m0, mx0), nm1 = fmaxf(m1, mx1);
        const float sc0 = __expf(m0 - nm0), sc1 = __expf(m1 - nm1);
        float rs0 = 0.f, rs1 = 0.f;
#pragma unroll
        for (int j = 0; j < 8; j++) {
            accS[j][0] = __expf(accS[j][0] - nm0);
            accS[j][1] = __expf(accS[j][1] - nm0);
            accS[j][2] = __expf(accS[j][2] - nm1);
            accS[j][3] = __expf(accS[j][3] - nm1);
            rs0 += accS[j][0] + accS[j][1];
            rs1 += accS[j][2] + accS[j][3];
        }
#pragma unroll
        for (int off = 1; off <= 2; off <<= 1) {
            rs0 += __shfl_xor_sync(0xffffffffu, rs0, off);
            rs1 += __shfl_xor_sync(0xffffffffu, rs1, off);
        }
        sum0 = sum0 * sc0 + rs0;
        sum1 = sum1 * sc1 + rs1;
        m0 = nm0; m1 = nm1;
#pragma unroll
        for (int j = 0; j < 8; j++) {
            o[j][0] *= sc0; o[j][1] *= sc0;
            o[j][2] *= sc1; o[j][3] *= sc1;
        }

        // O += P V  (P: acc-layout -> A-layout via quad shuffles; 3x tf32)
        const int sl0 = (lane & ~3) | (t >> 1);
        const int sl2 = sl0 + 2;
#pragma unroll
        for (int kt = 0; kt < 8; kt++) {
            float p00 = __shfl_sync(0xffffffffu, accS[kt][0], sl0);
            float p01 = __shfl_sync(0xffffffffu, accS[kt][1], sl0);
            float p20 = __shfl_sync(0xffffffffu, accS[kt][0], sl2);
            float p21 = __shfl_sync(0xffffffffu, accS[kt][1], sl2);
            float p10 = __shfl_sync(0xffffffffu, accS[kt][2], sl0);
            float p11 = __shfl_sync(0xffffffffu, accS[kt][3], sl0);
            float p30 = __shfl_sync(0xffffffffu, accS[kt][2], sl2);
            float p31 = __shfl_sync(0xffffffffu, accS[kt][3], sl2);
            float a0 = (t & 1) ? p01 : p00;   // P[g][8kt+t]
            float a1 = (t & 1) ? p11 : p10;   // P[g+8][8kt+t]
            float a2 = (t & 1) ? p21 : p20;   // P[g][8kt+t+4]
            float a3 = (t & 1) ? p31 : p30;   // P[g+8][8kt+t+4]
            uint32_t ah[4], al[4];
            ah[0] = f2tf32(a0); al[0] = f2tf32(a0 - __uint_as_float(ah[0]));
            ah[1] = f2tf32(a1); al[1] = f2tf32(a1 - __uint_as_float(ah[1]));
            ah[2] = f2tf32(a2); al[2] = f2tf32(a2 - __uint_as_float(ah[2]));
            ah[3] = f2tf32(a3); al[3] = f2tf32(a3 - __uint_as_float(ah[3]));

            const uint32_t ks = (uint32_t)kt * 32;
            uint32_t bv[16];
            ldsm4(bv + 0,  sVha + ks);
            ldsm4(bv + 4,  sVha + ks + R16);
            ldsm4(bv + 8,  sVha + ks + 2 * R16);
            ldsm4(bv + 12, sVha + ks + 3 * R16);
#pragma unroll
            for (int j = 0; j < 8; j++) {
                mma8(o[j], ah, bv + 2 * j);   // Ph * Vh
                mma8(o[j], al, bv + 2 * j);   // Pl * Vh
            }
            ldsm4(bv + 0,  sVla + ks);
            ldsm4(bv + 4,  sVla + ks + R16);
            ldsm4(bv + 8,  sVla + ks + 2 * R16);
            ldsm4(bv + 12, sVla + ks + 3 * R16);
#pragma unroll
            for (int j = 0; j < 8; j++)
                mma8(o[j], ah, bv + 2 * j);   // Ph * Vl
        }
    }

    // normalize + write
    const float inv0 = 1.f / sum0, inv1 = 1.f / sum1;
    float* ob = O + ((long)b * L_ + l0 + w * 16) * D_ + h * 64;
#pragma unroll
    for (int j = 0; j < 8; j++) {
        const int col = 8 * j + 2 * t;
        *(float2*)(ob + (long)g * D_ + col) =
            make_float2(o[j][0] * inv0, o[j][1] * inv0);
        *(float2*)(ob + (long)(g + 8) * D_ + col) =
            make_float2(o[j][2] * inv1, o[j][3] * inv1);
    }
}

// ---------------------------------------------------------------------------
extern "C" void kernel_launch(void* const* d_in, const int* in_sizes, int n_in,
                              void* d_out, int out_size)
{
    const float* query = (const float*)d_in[0];
    const float* key   = (const float*)d_in[1];
    const float* value = (const float*)d_in[2];
    const float* news  = (const float*)d_in[3];
    const float* Wq = (const float*)d_in[4];
    const float* bq = (const float*)d_in[5];
    const float* Wk = (const float*)d_in[6];
    const float* bk = (const float*)d_in[7];
    const float* Wv = (const float*)d_in[8];
    const float* bv = (const float*)d_in[9];
    const float* Wn = (const float*)d_in[10];
    const float* bn = (const float*)d_in[11];
    const float* Wo = (const float*)d_in[12];
    const float* bo = (const float*)d_in[13];
    // d_in[14] = pos. Mathematically irrelevant (swapaxes of swapped enh == enh).

    float *pq, *pk, *pv, *pn, *ptnk, *pink, *penh, *patt;
    cudaGetSymbolAddress((void**)&pq,   g_q);
    cudaGetSymbolAddress((void**)&pk,   g_k);
    cudaGetSymbolAddress((void**)&pv,   g_v);
    cudaGetSymbolAddress((void**)&pn,   g_n);
    cudaGetSymbolAddress((void**)&ptnk, g_tnk);
    cudaGetSymbolAddress((void**)&pink, g_ink);
    cudaGetSymbolAddress((void**)&penh, g_enh);
    cudaGetSymbolAddress((void**)&patt, g_att);

    const int M = B_ * L_;  // 8192
    dim3 blk(256);
    const int gsmem = 2 * STG_F * 4;  // 147456
    cudaFuncSetAttribute(tc_gemm, cudaFuncAttributeMaxDynamicSharedMemorySize, gsmem);

    // projections: x @ W^T + b
    tc_gemm<<<dim3(D_ / 128, M / 128, 1), blk, gsmem>>>(query, Wq, pq, bq, M, D_, D_, 0, 0, 0);
    tc_gemm<<<dim3(D_ / 128, M / 128, 1), blk, gsmem>>>(key,   Wk, pk, bk, M, D_, D_, 0, 0, 0);
    tc_gemm<<<dim3(D_ / 128, M / 128, 1), blk, gsmem>>>(value, Wv, pv, bv, M, D_, D_, 0, 0, 0);
    tc_gemm<<<dim3(D_ / 128, M / 128, 1), blk, gsmem>>>(news,  Wn, pn, bn, M, D_, D_, 0, 0, 0);

    // t_nk = q @ nk^T, i_nk = k @ nk^T (batched over B)
    tc_gemm<<<dim3(L_ / 128, L_ / 128, B_), blk, gsmem>>>(pq, pn, ptnk, nullptr,
        L_, L_, D_, (long)L_ * D_, (long)L_ * D_, (long)L_ * L_);
    tc_gemm<<<dim3(L_ / 128, L_ / 128, B_), blk, gsmem>>>(pk, pn, pink, nullptr,
        L_, L_, D_, (long)L_ * D_, (long)L_ * D_, (long)L_ * L_);

    // enh = t_nk @ i_nk^T (batched)
    tc_gemm<<<dim3(L_ / 128, L_ / 128, B_), blk, gsmem>>>(ptnk, pink, penh, nullptr,
        L_, L_, L_, (long)L_ * L_, (long)L_ * L_, (long)L_ * L_);

    // fused attention (QK^T + enh + softmax + PV), tensor-core path
    const int attn_smem = (128 * 68 + 3 * 64 * 68) * 4;  // 87040
    cudaFuncSetAttribute(attn_mma, cudaFuncAttributeMaxDynamicSharedMemorySize,
                         attn_smem);
    attn_mma<<<dim3(L_ / 128, B_ * H_), blk, attn_smem>>>(pq, pk, pv, penh, patt);

    // output projection -> d_out
    tc_gemm<<<dim3(D_ / 128, M / 128, 1), blk, gsmem>>>(patt, Wo, (float*)d_out, bo,
                                                        M, D_, D_, 0, 0, 0);
}

// round 5
// speedup vs baseline: 1.8414x; 1.1933x over previous
#include <cuda_runtime.h>
#include <stdint.h>

#define B_ 8
#define L_ 1024
#define D_ 768
#define H_ 12

// ---------------- scratch (device globals; no allocations allowed) ----------
__device__ float g_q[B_ * L_ * D_];
__device__ float g_k[B_ * L_ * D_];
__device__ float g_v[B_ * L_ * D_];
__device__ float g_n[B_ * L_ * D_];
__device__ float g_nkT[B_ * D_ * L_];          // nk transposed per batch
__device__ float g_G[B_ * D_ * D_];            // G = nk^T nk
__device__ float g_T[B_ * L_ * D_];            // T = q G
__device__ float g_enh[(long)B_ * L_ * L_];
__device__ float g_att[B_ * L_ * D_];

// ---------------- helpers ----------------------------------------------------
__device__ __forceinline__ uint32_t smem_u32(const void* p) {
    uint32_t a;
    asm("{ .reg .u64 t; cvta.to.shared.u64 t, %1; cvt.u32.u64 %0, t; }"
        : "=r"(a) : "l"(p));
    return a;
}
__device__ __forceinline__ uint32_t f2tf32(float x) {
    uint32_t r;
    asm("cvt.rna.tf32.f32 %0, %1;" : "=r"(r) : "f"(x));
    return r;
}
__device__ __forceinline__ void split4(float4 a, uint4& h, uint4& l) {
    h.x = f2tf32(a.x); l.x = f2tf32(a.x - __uint_as_float(h.x));
    h.y = f2tf32(a.y); l.y = f2tf32(a.y - __uint_as_float(h.y));
    h.z = f2tf32(a.z); l.z = f2tf32(a.z - __uint_as_float(h.z));
    h.w = f2tf32(a.w); l.w = f2tf32(a.w - __uint_as_float(h.w));
}
__device__ __forceinline__ uint4 hi4(float4 a) {
    uint4 h;
    h.x = f2tf32(a.x); h.y = f2tf32(a.y);
    h.z = f2tf32(a.z); h.w = f2tf32(a.w);
    return h;
}
__device__ __forceinline__ void ldsm4(uint32_t* r, uint32_t addr) {
    asm volatile("ldmatrix.sync.aligned.m8n8.x4.shared.b16 {%0,%1,%2,%3}, [%4];"
                 : "=r"(r[0]), "=r"(r[1]), "=r"(r[2]), "=r"(r[3]) : "r"(addr));
}
__device__ __forceinline__ void mma8(float* d, const uint32_t* a, const uint32_t* b) {
    asm volatile(
        "mma.sync.aligned.m16n8k8.row.col.f32.tf32.tf32.f32 "
        "{%0,%1,%2,%3}, {%4,%5,%6,%7}, {%8,%9}, {%0,%1,%2,%3};"
        : "+f"(d[0]), "+f"(d[1]), "+f"(d[2]), "+f"(d[3])
        : "r"(a[0]), "r"(a[1]), "r"(a[2]), "r"(a[3]), "r"(b[0]), "r"(b[1]));
}

// ---------------------------------------------------------------------------
// Error-compensated NT GEMM via mma.sync, 2-stage double buffer.
//   C[m,n] = sum_k A[m,k]*B[n,k] (+bias[n]).
// TERMS=3: AhBh + AhBl + AlBh (~fp32 accuracy). Stage = Ah/Al/Bh/Bl.
// TERMS=2: AhBh + AhBl (A unsplit; ~tf32-rounding-on-A error). Stage = Ah/Bh/Bl.
// CTA 128x128, K-chunk 32, 8 warps (2x4), warp tile 64x32.
// ---------------------------------------------------------------------------
template <int TERMS>
__global__ void __launch_bounds__(256) tc_gemm(
    const float* __restrict__ A, const float* __restrict__ B,
    float* __restrict__ C, const float* __restrict__ bias,
    int M, int N, int K, long sA, long sB, long sC)
{
    constexpr int NARR = (TERMS == 3) ? 4 : 3;
    constexpr int STGF = NARR * 4608;          // floats per stage
    extern __shared__ float sm[];
    const uint32_t smb = smem_u32(sm);

    const int tid = threadIdx.x;
    const int lane = tid & 31;
    const int warp = tid >> 5;
    const int wm = warp >> 2;
    const int wn = warp & 3;
    const int bm = blockIdx.y * 128;
    const int bn = blockIdx.x * 128;
    A += (long)blockIdx.z * sA;
    B += (long)blockIdx.z * sB;
    C += (long)blockIdx.z * sC;

    const int row0 = tid >> 3;
    const int c4 = (tid & 7) << 2;
    const float* Ap = A + (long)(bm + row0) * K + c4;
    const float* Bp = B + (long)(bn + row0) * K + c4;

    const uint32_t aOff =
        ((((uint32_t)(wm * 64 + (lane & 15)) * 36u) + ((lane & 16) >> 2)) << 2);
    const uint32_t bArr = (uint32_t)((TERMS == 3 ? 2 : 1) * 4608) << 2;
    const uint32_t bOff =
        ((((uint32_t)(wn * 32 + (lane & 7) + ((lane & 16) >> 1)) * 36u) +
          ((lane & 8) >> 1)) << 2) + bArr;

    float acc[4][4][4];
#pragma unroll
    for (int m = 0; m < 4; m++)
#pragma unroll
        for (int n = 0; n < 4; n++)
#pragma unroll
            for (int r = 0; r < 4; r++) acc[m][n][r] = 0.f;

    const int NC = K >> 5;

    // ---- prologue: chunk 0 -> stage 0
    {
        float4 av[4], bv[4];
#pragma unroll
        for (int it = 0; it < 4; it++) {
            av[it] = *(const float4*)(Ap + (long)(it * 32) * K);
            bv[it] = *(const float4*)(Bp + (long)(it * 32) * K);
        }
#pragma unroll
        for (int it = 0; it < 4; it++) {
            const int idx = (row0 + it * 32) * 36 + c4;
            uint4 h, l;
            if (TERMS == 3) {
                split4(av[it], h, l);
                *(uint4*)(sm + idx) = h;
                *(uint4*)(sm + 4608 + idx) = l;
                split4(bv[it], h, l);
                *(uint4*)(sm + 9216 + idx) = h;
                *(uint4*)(sm + 13824 + idx) = l;
            } else {
                *(uint4*)(sm + idx) = hi4(av[it]);
                split4(bv[it], h, l);
                *(uint4*)(sm + 4608 + idx) = h;
                *(uint4*)(sm + 9216 + idx) = l;
            }
        }
    }
    __syncthreads();

    for (int c = 0; c < NC; c++) {
        const int buf = c & 1;
        float4 av[4], bv[4];
        if (c + 1 < NC) {
            const int k0 = (c + 1) << 5;
#pragma unroll
            for (int it = 0; it < 4; it++) {
                av[it] = *(const float4*)(Ap + (long)(it * 32) * K + k0);
                bv[it] = *(const float4*)(Bp + (long)(it * 32) * K + k0);
            }
        }

        // MMA phase on stage `buf`
        const uint32_t stB = smb + (uint32_t)buf * (STGF << 2);
        const uint32_t aH = stB + aOff;
        const uint32_t bH = stB + bOff;
        const uint32_t bL = bH + (4608u << 2);
#pragma unroll
        for (int s = 0; s < 4; s++) {
            const uint32_t ks = (uint32_t)(s * 8) << 2;
            uint32_t bh[8], bl[8];
            ldsm4(bh + 0, bH + ks);
            ldsm4(bh + 4, bH + ks + (16 * 36 << 2));
            ldsm4(bl + 0, bL + ks);
            ldsm4(bl + 4, bL + ks + (16 * 36 << 2));
            uint32_t af[16];
#pragma unroll
            for (int m = 0; m < 4; m++)
                ldsm4(af + 4 * m, aH + ks + ((uint32_t)(m * 16 * 36) << 2));
#pragma unroll
            for (int m = 0; m < 4; m++)
#pragma unroll
                for (int n = 0; n < 4; n++) {
                    mma8(acc[m][n], af + 4 * m, bh + 2 * n);
                    mma8(acc[m][n], af + 4 * m, bl + 2 * n);
                }
            if (TERMS == 3) {
                const uint32_t aL = aH + (4608u << 2);
#pragma unroll
                for (int m = 0; m < 4; m++)
                    ldsm4(af + 4 * m, aL + ks + ((uint32_t)(m * 16 * 36) << 2));
#pragma unroll
                for (int m = 0; m < 4; m++)
#pragma unroll
                    for (int n = 0; n < 4; n++)
                        mma8(acc[m][n], af + 4 * m, bh + 2 * n);
            }
        }

        // split + STS chunk c+1 into stage buf^1
        if (c + 1 < NC) {
            float* st = sm + (buf ^ 1) * STGF;
#pragma unroll
            for (int it = 0; it < 4; it++) {
                const int idx = (row0 + it * 32) * 36 + c4;
                uint4 h, l;
                if (TERMS == 3) {
                    split4(av[it], h, l);
                    *(uint4*)(st + idx) = h;
                    *(uint4*)(st + 4608 + idx) = l;
                    split4(bv[it], h, l);
                    *(uint4*)(st + 9216 + idx) = h;
                    *(uint4*)(st + 13824 + idx) = l;
                } else {
                    *(uint4*)(st + idx) = hi4(av[it]);
                    split4(bv[it], h, l);
                    *(uint4*)(st + 4608 + idx) = h;
                    *(uint4*)(st + 9216 + idx) = l;
                }
            }
        }
        __syncthreads();
    }

    // epilogue: registers -> gmem
    const int g = lane >> 2;
    const int t = lane & 3;
#pragma unroll
    for (int n = 0; n < 4; n++) {
        const int col = bn + wn * 32 + n * 8 + t * 2;
        float b0 = 0.f, b1 = 0.f;
        if (bias) { b0 = bias[col]; b1 = bias[col + 1]; }
#pragma unroll
        for (int m = 0; m < 4; m++) {
            const int r0 = bm + wm * 64 + m * 16 + g;
            float2 v0 = make_float2(acc[m][n][0] + b0, acc[m][n][1] + b1);
            float2 v1 = make_float2(acc[m][n][2] + b0, acc[m][n][3] + b1);
            *(float2*)(C + (long)r0 * N + col) = v0;
            *(float2*)(C + (long)(r0 + 8) * N + col) = v1;
        }
    }
}

// ---------------------------------------------------------------------------
// Batched transpose: in [B][L][D] -> out [B][D][L]
// ---------------------------------------------------------------------------
__global__ void transpose_ld(const float* __restrict__ in, float* __restrict__ out)
{
    __shared__ float t[32][33];
    const int b = blockIdx.z;
    const int d0 = blockIdx.x * 32;
    const int l0 = blockIdx.y * 32;
    const int x = threadIdx.x;
    const int y = threadIdx.y;
    const float* ib = in + ((long)b * L_ + l0) * D_ + d0;
#pragma unroll
    for (int i = y; i < 32; i += 8) t[i][x] = ib[(long)i * D_ + x];
    __syncthreads();
    float* ob = out + ((long)b * D_ + d0) * L_ + l0;
#pragma unroll
    for (int i = y; i < 32; i += 8) ob[(long)i * L_ + x] = t[x][i];
}

// ---------------------------------------------------------------------------
// Fused attention via mma.sync.
// Block = 128 q-rows x (b,h). Warp w owns rows w*16..w*16+15.
//   S = QK^T (1x tf32) ; S = (S+E)/16 ; online softmax ;
//   O = P V (2-term: Ph*Vh + Ph*Vl).
// ---------------------------------------------------------------------------
__global__ void __launch_bounds__(256, 2) attn_mma(
    const float* __restrict__ Q, const float* __restrict__ K,
    const float* __restrict__ V, const float* __restrict__ E,
    float* __restrict__ O)
{
    extern __shared__ float sh[];
    float* sQ = sh;                    // 128*68
    float* sK = sh + 128 * 68;         // 64*68
    float* sVh = sK + 64 * 68;         // [d][key]
    float* sVl = sVh + 64 * 68;

    const int b = blockIdx.y / H_;
    const int h = blockIdx.y % H_;
    const int l0 = blockIdx.x * 128;
    const int tid = threadIdx.x;
    const int lane = tid & 31;
    const int w = tid >> 5;
    const int g = lane >> 2;
    const int t = lane & 3;

    const float* qb = Q + ((long)b * L_ + l0) * D_ + h * 64;
    const float* kb = K + (long)b * L_ * D_ + h * 64;
    const float* vb = V + (long)b * L_ * D_ + h * 64;
    const float* e0 = E + ((long)b * L_ + l0 + w * 16 + g) * L_;
    const float* e1 = e0 + 8 * L_;

#pragma unroll
    for (int it = 0; it < 8; it++) {
        int f = tid + it * 256;
        int row = f >> 4;
        int d4 = (f & 15) << 2;
        float4 v = *(const float4*)(qb + (long)row * D_ + d4);
        *(uint4*)(sQ + row * 68 + d4) = hi4(v);
    }

    const uint32_t sQa = smem_u32(sQ) +
        ((((uint32_t)(w * 16 + (lane & 15)) * 68u) + ((lane & 16) >> 2)) << 2);
    const uint32_t bPat =
        ((((uint32_t)((lane & 7) + ((lane & 16) >> 1)) * 68u) +
          ((lane & 8) >> 1)) << 2);
    const uint32_t sKa = smem_u32(sK) + bPat;
    const uint32_t sVha = smem_u32(sVh) + bPat;
    const uint32_t sVla = smem_u32(sVl) + bPat;
    const uint32_t R16 = (16 * 68) << 2;

    float o[8][4];
#pragma unroll
    for (int j = 0; j < 8; j++)
#pragma unroll
        for (int r = 0; r < 4; r++) o[j][r] = 0.f;
    float m0 = -1e30f, m1 = -1e30f, sum0 = 0.f, sum1 = 0.f;

    for (int jb = 0; jb < 16; jb++) {
        __syncthreads();
#pragma unroll
        for (int it = 0; it < 4; it++) {
            int f = tid + it * 256;
            int key = f >> 4;
            int d4 = (f & 15) << 2;
            float4 v = *(const float4*)(kb + (long)(jb * 64 + key) * D_ + d4);
            *(uint4*)(sK + key * 68 + d4) = hi4(v);
        }
#pragma unroll
        for (int it = 0; it < 4; it++) {
            int f = tid + it * 256;
            int key = f >> 4;
            int d4 = (f & 15) << 2;
            float4 v = *(const float4*)(vb + (long)(jb * 64 + key) * D_ + d4);
            float vv[4] = {v.x, v.y, v.z, v.w};
#pragma unroll
            for (int i = 0; i < 4; i++) {
                uint32_t hi = f2tf32(vv[i]);
                uint32_t lo = f2tf32(vv[i] - __uint_as_float(hi));
                *(uint32_t*)(sVh + (d4 + i) * 68 + key) = hi;
                *(uint32_t*)(sVl + (d4 + i) * 68 + key) = lo;
            }
        }
        __syncthreads();

        // S = Q K^T
        float accS[8][4];
#pragma unroll
        for (int j = 0; j < 8; j++)
#pragma unroll
            for (int r = 0; r < 4; r++) accS[j][r] = 0.f;
#pragma unroll
        for (int s = 0; s < 8; s++) {
            const uint32_t ks = (uint32_t)s * 32;
            uint32_t af[4], bf[16];
            ldsm4(af, sQa + ks);
            ldsm4(bf + 0,  sKa + ks);
            ldsm4(bf + 4,  sKa + ks + R16);
            ldsm4(bf + 8,  sKa + ks + 2 * R16);
            ldsm4(bf + 12, sKa + ks + 3 * R16);
#pragma unroll
            for (int j = 0; j < 8; j++) mma8(accS[j], af, bf + 2 * j);
        }

        // add E, scale by 1/16
#pragma unroll
        for (int j = 0; j < 8; j++) {
            const int col = jb * 64 + 8 * j + 2 * t;
            float2 ea = *(const float2*)(e0 + col);
            float2 ebv = *(const float2*)(e1 + col);
            accS[j][0] = (accS[j][0] + ea.x) * 0.0625f;
            accS[j][1] = (accS[j][1] + ea.y) * 0.0625f;
            accS[j][2] = (accS[j][2] + ebv.x) * 0.0625f;
            accS[j][3] = (accS[j][3] + ebv.y) * 0.0625f;
        }

        // online softmax
        float mx0 = -1e30f, mx1 = -1e30f;
#pragma unroll
        for (int j = 0; j < 8; j++) {
            mx0 = fmaxf(mx0, fmaxf(accS[j][0], accS[j][1]));
            mx1 = fmaxf(mx1, fmaxf(accS[j][2], accS[j][3]));
        }
#pragma unroll
        for (int off = 1; off <= 2; off <<= 1) {
            mx0 = fmaxf(mx0, __shfl_xor_sync(0xffffffffu, mx0, off));
            mx1 = fmaxf(mx1, __shfl_xor_sync(0xffffffffu, mx1, off));
        }
        const float nm0 = fmaxf(m0, mx0), nm1 = fmaxf(m1, mx1);
        const float sc0 = __expf(m0 - nm0), sc1 = __expf(m1 - nm1);
        float rs0 = 0.f, rs1 = 0.f;
#pragma unroll
        for (int j = 0; j < 8; j++) {
            accS[j][0] = __expf(accS[j][0] - nm0);
            accS[j][1] = __expf(accS[j][1] - nm0);
            accS[j][2] = __expf(accS[j][2] - nm1);
            accS[j][3] = __expf(accS[j][3] - nm1);
            rs0 += accS[j][0] + accS[j][1];
            rs1 += accS[j][2] + accS[j][3];
        }
#pragma unroll
        for (int off = 1; off <= 2; off <<= 1) {
            rs0 += __shfl_xor_sync(0xffffffffu, rs0, off);
            rs1 += __shfl_xor_sync(0xffffffffu, rs1, off);
        }
        sum0 = sum0 * sc0 + rs0;
        sum1 = sum1 * sc1 + rs1;
        m0 = nm0; m1 = nm1;
#pragma unroll
        for (int j = 0; j < 8; j++) {
            o[j][0] *= sc0; o[j][1] *= sc0;
            o[j][2] *= sc1; o[j][3] *= sc1;
        }

        // O += P V  (acc-layout -> A-layout via quad shuffles; 2-term)
        const int sl0 = (lane & ~3) | (t >> 1);
        const int sl2 = sl0 + 2;
#pragma unroll
        for (int kt = 0; kt < 8; kt++) {
            float p00 = __shfl_sync(0xffffffffu, accS[kt][0], sl0);
            float p01 = __shfl_sync(0xffffffffu, accS[kt][1], sl0);
            float p20 = __shfl_sync(0xffffffffu, accS[kt][0], sl2);
            float p21 = __shfl_sync(0xffffffffu, accS[kt][1], sl2);
            float p10 = __shfl_sync(0xffffffffu, accS[kt][2], sl0);
            float p11 = __shfl_sync(0xffffffffu, accS[kt][3], sl0);
            float p30 = __shfl_sync(0xffffffffu, accS[kt][2], sl2);
            float p31 = __shfl_sync(0xffffffffu, accS[kt][3], sl2);
            float a0 = (t & 1) ? p01 : p00;
            float a1 = (t & 1) ? p11 : p10;
            float a2 = (t & 1) ? p21 : p20;
            float a3 = (t & 1) ? p31 : p30;
            uint32_t ah[4];
            ah[0] = f2tf32(a0); ah[1] = f2tf32(a1);
            ah[2] = f2tf32(a2); ah[3] = f2tf32(a3);

            const uint32_t ks = (uint32_t)kt * 32;
            uint32_t bv[16];
            ldsm4(bv + 0,  sVha + ks);
            ldsm4(bv + 4,  sVha + ks + R16);
            ldsm4(bv + 8,  sVha + ks + 2 * R16);
            ldsm4(bv + 12, sVha + ks + 3 * R16);
#pragma unroll
            for (int j = 0; j < 8; j++)
                mma8(o[j], ah, bv + 2 * j);   // Ph * Vh
            ldsm4(bv + 0,  sVla + ks);
            ldsm4(bv + 4,  sVla + ks + R16);
            ldsm4(bv + 8,  sVla + ks + 2 * R16);
            ldsm4(bv + 12, sVla + ks + 3 * R16);
#pragma unroll
            for (int j = 0; j < 8; j++)
                mma8(o[j], ah, bv + 2 * j);   // Ph * Vl
        }
    }

    const float inv0 = 1.f / sum0, inv1 = 1.f / sum1;
    float* ob = O + ((long)b * L_ + l0 + w * 16) * D_ + h * 64;
#pragma unroll
    for (int j = 0; j < 8; j++) {
        const int col = 8 * j + 2 * t;
        *(float2*)(ob + (long)g * D_ + col) =
            make_float2(o[j][0] * inv0, o[j][1] * inv0);
        *(float2*)(ob + (long)(g + 8) * D_ + col) =
            make_float2(o[j][2] * inv1, o[j][3] * inv1);
    }
}

// ---------------------------------------------------------------------------
extern "C" void kernel_launch(void* const* d_in, const int* in_sizes, int n_in,
                              void* d_out, int out_size)
{
    const float* query = (const float*)d_in[0];
    const float* key   = (const float*)d_in[1];
    const float* value = (const float*)d_in[2];
    const float* news  = (const float*)d_in[3];
    const float* Wq = (const float*)d_in[4];
    const float* bq = (const float*)d_in[5];
    const float* Wk = (const float*)d_in[6];
    const float* bk = (const float*)d_in[7];
    const float* Wv = (const float*)d_in[8];
    const float* bv = (const float*)d_in[9];
    const float* Wn = (const float*)d_in[10];
    const float* bn = (const float*)d_in[11];
    const float* Wo = (const float*)d_in[12];
    const float* bo = (const float*)d_in[13];
    // d_in[14] = pos. Mathematically irrelevant (swapaxes of swapped enh == enh).

    float *pq, *pk, *pv, *pn, *pnkT, *pG, *pT, *penh, *patt;
    cudaGetSymbolAddress((void**)&pq,   g_q);
    cudaGetSymbolAddress((void**)&pk,   g_k);
    cudaGetSymbolAddress((void**)&pv,   g_v);
    cudaGetSymbolAddress((void**)&pn,   g_n);
    cudaGetSymbolAddress((void**)&pnkT, g_nkT);
    cudaGetSymbolAddress((void**)&pG,   g_G);
    cudaGetSymbolAddress((void**)&pT,   g_T);
    cudaGetSymbolAddress((void**)&penh, g_enh);
    cudaGetSymbolAddress((void**)&patt, g_att);

    const int M = B_ * L_;  // 8192
    dim3 blk(256);
    const int smem3 = 2 * 4 * 4608 * 4;  // 147456
    const int smem2 = 2 * 3 * 4608 * 4;  // 110592
    cudaFuncSetAttribute(tc_gemm<3>, cudaFuncAttributeMaxDynamicSharedMemorySize, smem3);
    cudaFuncSetAttribute(tc_gemm<2>, cudaFuncAttributeMaxDynamicSharedMemorySize, smem2);

    // projections (q,k,nk on 3-term; v on 2-term)
    tc_gemm<3><<<dim3(D_ / 128, M / 128, 1), blk, smem3>>>(query, Wq, pq, bq, M, D_, D_, 0, 0, 0);
    tc_gemm<3><<<dim3(D_ / 128, M / 128, 1), blk, smem3>>>(key,   Wk, pk, bk, M, D_, D_, 0, 0, 0);
    tc_gemm<3><<<dim3(D_ / 128, M / 128, 1), blk, smem3>>>(news,  Wn, pn, bn, M, D_, D_, 0, 0, 0);
    tc_gemm<2><<<dim3(D_ / 128, M / 128, 1), blk, smem2>>>(value, Wv, pv, bv, M, D_, D_, 0, 0, 0);

    // enh = q (nk^T nk) k^T, restructured:
    // 1. nkT[b] = nk[b]^T
    transpose_ld<<<dim3(D_ / 32, L_ / 32, B_), dim3(32, 8)>>>(pn, pnkT);
    // 2. G[b] = nkT nkT^T = nk^T nk  (768x768, K=1024)
    tc_gemm<3><<<dim3(D_ / 128, D_ / 128, B_), blk, smem3>>>(pnkT, pnkT, pG, nullptr,
        D_, D_, L_, (long)D_ * L_, (long)D_ * L_, (long)D_ * D_);
    // 3. T[b] = q G  (G symmetric -> NT form valid)
    tc_gemm<3><<<dim3(D_ / 128, L_ / 128, B_), blk, smem3>>>(pq, pG, pT, nullptr,
        L_, D_, D_, (long)L_ * D_, (long)D_ * D_, (long)L_ * D_);
    // 4. enh[b] = T k^T
    tc_gemm<3><<<dim3(L_ / 128, L_ / 128, B_), blk, smem3>>>(pT, pk, penh, nullptr,
        L_, L_, D_, (long)L_ * D_, (long)L_ * D_, (long)L_ * L_);

    // fused attention
    const int attn_smem = (128 * 68 + 3 * 64 * 68) * 4;  // 87040
    cudaFuncSetAttribute(attn_mma, cudaFuncAttributeMaxDynamicSharedMemorySize,
                         attn_smem);
    attn_mma<<<dim3(L_ / 128, B_ * H_), blk, attn_smem>>>(pq, pk, pv, penh, patt);

    // output projection (2-term) -> d_out
    tc_gemm<2><<<dim3(D_ / 128, M / 128, 1), blk, smem2>>>(patt, Wo, (float*)d_out, bo,
                                                           M, D_, D_, 0, 0, 0);
}

// round 6
// speedup vs baseline: 1.9954x; 1.0836x over previous
#include <cuda_runtime.h>
#include <stdint.h>

#define B_ 8
#define L_ 1024
#define D_ 768
#define H_ 12

// ---------------- scratch (device globals; no allocations allowed) ----------
__device__ float g_q[B_ * L_ * D_];
__device__ float g_k[B_ * L_ * D_];
__device__ float g_v[B_ * L_ * D_];
__device__ float g_n[B_ * L_ * D_];
__device__ float g_nkT[B_ * D_ * L_];          // nk transposed per batch
__device__ float g_G[B_ * D_ * D_];            // G = nk^T nk
__device__ float g_T[B_ * L_ * D_];            // T = q G
__device__ float g_enh[(long)B_ * L_ * L_];
__device__ float g_att[B_ * L_ * D_];

// ---------------- helpers ----------------------------------------------------
__device__ __forceinline__ uint32_t smem_u32(const void* p) {
    uint32_t a;
    asm("{ .reg .u64 t; cvta.to.shared.u64 t, %1; cvt.u32.u64 %0, t; }"
        : "=r"(a) : "l"(p));
    return a;
}
__device__ __forceinline__ uint32_t f2tf32(float x) {
    uint32_t r;
    asm("cvt.rna.tf32.f32 %0, %1;" : "=r"(r) : "f"(x));
    return r;
}
__device__ __forceinline__ void split4(float4 a, uint4& h, uint4& l) {
    h.x = f2tf32(a.x); l.x = f2tf32(a.x - __uint_as_float(h.x));
    h.y = f2tf32(a.y); l.y = f2tf32(a.y - __uint_as_float(h.y));
    h.z = f2tf32(a.z); l.z = f2tf32(a.z - __uint_as_float(h.z));
    h.w = f2tf32(a.w); l.w = f2tf32(a.w - __uint_as_float(h.w));
}
__device__ __forceinline__ uint4 hi4(float4 a) {
    uint4 h;
    h.x = f2tf32(a.x); h.y = f2tf32(a.y);
    h.z = f2tf32(a.z); h.w = f2tf32(a.w);
    return h;
}
__device__ __forceinline__ void ldsm4(uint32_t* r, uint32_t addr) {
    asm volatile("ldmatrix.sync.aligned.m8n8.x4.shared.b16 {%0,%1,%2,%3}, [%4];"
                 : "=r"(r[0]), "=r"(r[1]), "=r"(r[2]), "=r"(r[3]) : "r"(addr));
}
__device__ __forceinline__ void mma8(float* d, const uint32_t* a, const uint32_t* b) {
    asm volatile(
        "mma.sync.aligned.m16n8k8.row.col.f32.tf32.tf32.f32 "
        "{%0,%1,%2,%3}, {%4,%5,%6,%7}, {%8,%9}, {%0,%1,%2,%3};"
        : "+f"(d[0]), "+f"(d[1]), "+f"(d[2]), "+f"(d[3])
        : "r"(a[0]), "r"(a[1]), "r"(a[2]), "r"(a[3]), "r"(b[0]), "r"(b[1]));
}

// ---------------------------------------------------------------------------
// Shared GEMM core pieces (CTA 128x128, K-chunk 32, 8 warps 2x4, warp 64x32).
// Stage layout (floats): Ah[4608] Al[4608] Bh[4608] Bl[4608]; 2 stages.
// ---------------------------------------------------------------------------
#define STG4 18432  // 4*4608

// ---------------------------------------------------------------------------
// Generic error-compensated NT GEMM (template TERMS = 2 or 3), double-buffered.
// ---------------------------------------------------------------------------
template <int TERMS>
__global__ void __launch_bounds__(256) tc_gemm(
    const float* __restrict__ A, const float* __restrict__ B,
    float* __restrict__ C, const float* __restrict__ bias,
    int M, int N, int K, long sA, long sB, long sC)
{
    constexpr int NARR = (TERMS == 3) ? 4 : 3;
    constexpr int STGF = NARR * 4608;
    extern __shared__ float sm[];
    const uint32_t smb = smem_u32(sm);

    const int tid = threadIdx.x;
    const int lane = tid & 31;
    const int warp = tid >> 5;
    const int wm = warp >> 2;
    const int wn = warp & 3;
    const int bm = blockIdx.y * 128;
    const int bn = blockIdx.x * 128;
    A += (long)blockIdx.z * sA;
    B += (long)blockIdx.z * sB;
    C += (long)blockIdx.z * sC;

    const int row0 = tid >> 3;
    const int c4 = (tid & 7) << 2;
    const float* Ap = A + (long)(bm + row0) * K + c4;
    const float* Bp = B + (long)(bn + row0) * K + c4;

    const uint32_t aOff =
        ((((uint32_t)(wm * 64 + (lane & 15)) * 36u) + ((lane & 16) >> 2)) << 2);
    const uint32_t bArr = (uint32_t)((TERMS == 3 ? 2 : 1) * 4608) << 2;
    const uint32_t bOff =
        ((((uint32_t)(wn * 32 + (lane & 7) + ((lane & 16) >> 1)) * 36u) +
          ((lane & 8) >> 1)) << 2) + bArr;

    float acc[4][4][4];
#pragma unroll
    for (int m = 0; m < 4; m++)
#pragma unroll
        for (int n = 0; n < 4; n++)
#pragma unroll
            for (int r = 0; r < 4; r++) acc[m][n][r] = 0.f;

    const int NC = K >> 5;

    {
        float4 av[4], bv[4];
#pragma unroll
        for (int it = 0; it < 4; it++) {
            av[it] = *(const float4*)(Ap + (long)(it * 32) * K);
            bv[it] = *(const float4*)(Bp + (long)(it * 32) * K);
        }
#pragma unroll
        for (int it = 0; it < 4; it++) {
            const int idx = (row0 + it * 32) * 36 + c4;
            uint4 h, l;
            if (TERMS == 3) {
                split4(av[it], h, l);
                *(uint4*)(sm + idx) = h;
                *(uint4*)(sm + 4608 + idx) = l;
                split4(bv[it], h, l);
                *(uint4*)(sm + 9216 + idx) = h;
                *(uint4*)(sm + 13824 + idx) = l;
            } else {
                *(uint4*)(sm + idx) = hi4(av[it]);
                split4(bv[it], h, l);
                *(uint4*)(sm + 4608 + idx) = h;
                *(uint4*)(sm + 9216 + idx) = l;
            }
        }
    }
    __syncthreads();

    for (int c = 0; c < NC; c++) {
        const int buf = c & 1;
        float4 av[4], bv[4];
        if (c + 1 < NC) {
            const int k0 = (c + 1) << 5;
#pragma unroll
            for (int it = 0; it < 4; it++) {
                av[it] = *(const float4*)(Ap + (long)(it * 32) * K + k0);
                bv[it] = *(const float4*)(Bp + (long)(it * 32) * K + k0);
            }
        }

        const uint32_t stB = smb + (uint32_t)buf * (STGF << 2);
        const uint32_t aH = stB + aOff;
        const uint32_t bH = stB + bOff;
        const uint32_t bL = bH + (4608u << 2);
#pragma unroll
        for (int s = 0; s < 4; s++) {
            const uint32_t ks = (uint32_t)(s * 8) << 2;
            uint32_t bh[8], bl[8];
            ldsm4(bh + 0, bH + ks);
            ldsm4(bh + 4, bH + ks + (16 * 36 << 2));
            ldsm4(bl + 0, bL + ks);
            ldsm4(bl + 4, bL + ks + (16 * 36 << 2));
            uint32_t af[16];
#pragma unroll
            for (int m = 0; m < 4; m++)
                ldsm4(af + 4 * m, aH + ks + ((uint32_t)(m * 16 * 36) << 2));
#pragma unroll
            for (int m = 0; m < 4; m++)
#pragma unroll
                for (int n = 0; n < 4; n++) {
                    mma8(acc[m][n], af + 4 * m, bh + 2 * n);
                    mma8(acc[m][n], af + 4 * m, bl + 2 * n);
                }
            if (TERMS == 3) {
                const uint32_t aL = aH + (4608u << 2);
#pragma unroll
                for (int m = 0; m < 4; m++)
                    ldsm4(af + 4 * m, aL + ks + ((uint32_t)(m * 16 * 36) << 2));
#pragma unroll
                for (int m = 0; m < 4; m++)
#pragma unroll
                    for (int n = 0; n < 4; n++)
                        mma8(acc[m][n], af + 4 * m, bh + 2 * n);
            }
        }

        if (c + 1 < NC) {
            float* st = sm + (buf ^ 1) * STGF;
#pragma unroll
            for (int it = 0; it < 4; it++) {
                const int idx = (row0 + it * 32) * 36 + c4;
                uint4 h, l;
                if (TERMS == 3) {
                    split4(av[it], h, l);
                    *(uint4*)(st + idx) = h;
                    *(uint4*)(st + 4608 + idx) = l;
                    split4(bv[it], h, l);
                    *(uint4*)(st + 9216 + idx) = h;
                    *(uint4*)(st + 13824 + idx) = l;
                } else {
                    *(uint4*)(st + idx) = hi4(av[it]);
                    split4(bv[it], h, l);
                    *(uint4*)(st + 4608 + idx) = h;
                    *(uint4*)(st + 9216 + idx) = l;
                }
            }
        }
        __syncthreads();
    }

    const int g = lane >> 2;
    const int t = lane & 3;
#pragma unroll
    for (int n = 0; n < 4; n++) {
        const int col = bn + wn * 32 + n * 8 + t * 2;
        float b0 = 0.f, b1 = 0.f;
        if (bias) { b0 = bias[col]; b1 = bias[col + 1]; }
#pragma unroll
        for (int m = 0; m < 4; m++) {
            const int r0 = bm + wm * 64 + m * 16 + g;
            float2 v0 = make_float2(acc[m][n][0] + b0, acc[m][n][1] + b1);
            float2 v1 = make_float2(acc[m][n][2] + b0, acc[m][n][3] + b1);
            *(float2*)(C + (long)r0 * N + col) = v0;
            *(float2*)(C + (long)(r0 + 8) * N + col) = v1;
        }
    }
}

// ---------------------------------------------------------------------------
// Merged projection GEMM: blockIdx.z selects (input, W, bias, output).
// z in 0..3 (q,k,nk 3-term; z==3 -> v, 2-term). M=8192, N=K=768.
// Uses the 4-array stage layout for all z (Al unused when z==3).
// ---------------------------------------------------------------------------
struct ProjArgs {
    const float* in[4];
    const float* W[4];
    const float* bias[4];
    float* out[4];
};

__global__ void __launch_bounds__(256) tc_proj(ProjArgs p)
{
    extern __shared__ float sm[];
    const uint32_t smb = smem_u32(sm);
    const int z = blockIdx.z;
    const bool three = (z != 3);
    const float* A = p.in[z];
    const float* B = p.W[z];
    const float* bias = p.bias[z];
    float* C = p.out[z];
    const int Kd = D_;
    const int Nd = D_;

    const int tid = threadIdx.x;
    const int lane = tid & 31;
    const int warp = tid >> 5;
    const int wm = warp >> 2;
    const int wn = warp & 3;
    const int bm = blockIdx.y * 128;
    const int bn = blockIdx.x * 128;

    const int row0 = tid >> 3;
    const int c4 = (tid & 7) << 2;
    const float* Ap = A + (long)(bm + row0) * Kd + c4;
    const float* Bp = B + (long)(bn + row0) * Kd + c4;

    const uint32_t aOff =
        ((((uint32_t)(wm * 64 + (lane & 15)) * 36u) + ((lane & 16) >> 2)) << 2);
    const uint32_t bOff =
        ((((uint32_t)(wn * 32 + (lane & 7) + ((lane & 16) >> 1)) * 36u) +
          ((lane & 8) >> 1)) << 2) + ((2 * 4608) << 2);

    float acc[4][4][4];
#pragma unroll
    for (int m = 0; m < 4; m++)
#pragma unroll
        for (int n = 0; n < 4; n++)
#pragma unroll
            for (int r = 0; r < 4; r++) acc[m][n][r] = 0.f;

    const int NC = Kd >> 5;

    {
        float4 av[4], bv[4];
#pragma unroll
        for (int it = 0; it < 4; it++) {
            av[it] = *(const float4*)(Ap + (long)(it * 32) * Kd);
            bv[it] = *(const float4*)(Bp + (long)(it * 32) * Kd);
        }
#pragma unroll
        for (int it = 0; it < 4; it++) {
            const int idx = (row0 + it * 32) * 36 + c4;
            uint4 h, l;
            split4(av[it], h, l);
            *(uint4*)(sm + idx) = h;
            if (three) *(uint4*)(sm + 4608 + idx) = l;
            split4(bv[it], h, l);
            *(uint4*)(sm + 9216 + idx) = h;
            *(uint4*)(sm + 13824 + idx) = l;
        }
    }
    __syncthreads();

    for (int c = 0; c < NC; c++) {
        const int buf = c & 1;
        float4 av[4], bv[4];
        if (c + 1 < NC) {
            const int k0 = (c + 1) << 5;
#pragma unroll
            for (int it = 0; it < 4; it++) {
                av[it] = *(const float4*)(Ap + (long)(it * 32) * Kd + k0);
                bv[it] = *(const float4*)(Bp + (long)(it * 32) * Kd + k0);
            }
        }

        const uint32_t stB = smb + (uint32_t)buf * (STG4 << 2);
        const uint32_t aH = stB + aOff;
        const uint32_t bH = stB + bOff;
        const uint32_t bL = bH + (4608u << 2);
#pragma unroll
        for (int s = 0; s < 4; s++) {
            const uint32_t ks = (uint32_t)(s * 8) << 2;
            uint32_t bh[8], bl[8];
            ldsm4(bh + 0, bH + ks);
            ldsm4(bh + 4, bH + ks + (16 * 36 << 2));
            ldsm4(bl + 0, bL + ks);
            ldsm4(bl + 4, bL + ks + (16 * 36 << 2));
            uint32_t af[16];
#pragma unroll
            for (int m = 0; m < 4; m++)
                ldsm4(af + 4 * m, aH + ks + ((uint32_t)(m * 16 * 36) << 2));
#pragma unroll
            for (int m = 0; m < 4; m++)
#pragma unroll
                for (int n = 0; n < 4; n++) {
                    mma8(acc[m][n], af + 4 * m, bh + 2 * n);
                    mma8(acc[m][n], af + 4 * m, bl + 2 * n);
                }
            if (three) {
                const uint32_t aL = aH + (4608u << 2);
#pragma unroll
                for (int m = 0; m < 4; m++)
                    ldsm4(af + 4 * m, aL + ks + ((uint32_t)(m * 16 * 36) << 2));
#pragma unroll
                for (int m = 0; m < 4; m++)
#pragma unroll
                    for (int n = 0; n < 4; n++)
                        mma8(acc[m][n], af + 4 * m, bh + 2 * n);
            }
        }

        if (c + 1 < NC) {
            float* st = sm + (buf ^ 1) * STG4;
#pragma unroll
            for (int it = 0; it < 4; it++) {
                const int idx = (row0 + it * 32) * 36 + c4;
                uint4 h, l;
                split4(av[it], h, l);
                *(uint4*)(st + idx) = h;
                if (three) *(uint4*)(st + 4608 + idx) = l;
                split4(bv[it], h, l);
                *(uint4*)(st + 9216 + idx) = h;
                *(uint4*)(st + 13824 + idx) = l;
            }
        }
        __syncthreads();
    }

    const int g = lane >> 2;
    const int t = lane & 3;
#pragma unroll
    for (int n = 0; n < 4; n++) {
        const int col = bn + wn * 32 + n * 8 + t * 2;
        const float b0 = bias[col];
        const float b1 = bias[col + 1];
#pragma unroll
        for (int m = 0; m < 4; m++) {
            const int r0 = bm + wm * 64 + m * 16 + g;
            float2 v0 = make_float2(acc[m][n][0] + b0, acc[m][n][1] + b1);
            float2 v1 = make_float2(acc[m][n][2] + b0, acc[m][n][3] + b1);
            *(float2*)(C + (long)r0 * Nd + col) = v0;
            *(float2*)(C + (long)(r0 + 8) * Nd + col) = v1;
        }
    }
}

// ---------------------------------------------------------------------------
// Batched transpose: in [B][L][D] -> out [B][D][L]
// ---------------------------------------------------------------------------
__global__ void transpose_ld(const float* __restrict__ in, float* __restrict__ out)
{
    __shared__ float t[32][33];
    const int b = blockIdx.z;
    const int d0 = blockIdx.x * 32;
    const int l0 = blockIdx.y * 32;
    const int x = threadIdx.x;
    const int y = threadIdx.y;
    const float* ib = in + ((long)b * L_ + l0) * D_ + d0;
#pragma unroll
    for (int i = y; i < 32; i += 8) t[i][x] = ib[(long)i * D_ + x];
    __syncthreads();
    float* ob = out + ((long)b * D_ + d0) * L_ + l0;
#pragma unroll
    for (int i = y; i < 32; i += 8) ob[(long)i * L_ + x] = t[x][i];
}

// ---------------------------------------------------------------------------
// Fused attention via mma.sync.
//   S = QK^T (1x tf32) ; S = (S+E)/16 ; online softmax ; O = P V (1x tf32).
// smem: sQ[128][68] + sK[64][68] + sVh[64][68] = 69632 B.
// ---------------------------------------------------------------------------
__global__ void __launch_bounds__(256, 2) attn_mma(
    const float* __restrict__ Q, const float* __restrict__ K,
    const float* __restrict__ V, const float* __restrict__ E,
    float* __restrict__ O)
{
    extern __shared__ float sh[];
    float* sQ = sh;                    // 128*68
    float* sK = sh + 128 * 68;         // 64*68
    float* sVh = sK + 64 * 68;         // [d][key]

    const int b = blockIdx.y / H_;
    const int h = blockIdx.y % H_;
    const int l0 = blockIdx.x * 128;
    const int tid = threadIdx.x;
    const int lane = tid & 31;
    const int w = tid >> 5;
    const int g = lane >> 2;
    const int t = lane & 3;

    const float* qb = Q + ((long)b * L_ + l0) * D_ + h * 64;
    const float* kb = K + (long)b * L_ * D_ + h * 64;
    const float* vb = V + (long)b * L_ * D_ + h * 64;
    const float* e0 = E + ((long)b * L_ + l0 + w * 16 + g) * L_;
    const float* e1 = e0 + 8 * L_;

#pragma unroll
    for (int it = 0; it < 8; it++) {
        int f = tid + it * 256;
        int row = f >> 4;
        int d4 = (f & 15) << 2;
        float4 v = *(const float4*)(qb + (long)row * D_ + d4);
        *(uint4*)(sQ + row * 68 + d4) = hi4(v);
    }

    const uint32_t sQa = smem_u32(sQ) +
        ((((uint32_t)(w * 16 + (lane & 15)) * 68u) + ((lane & 16) >> 2)) << 2);
    const uint32_t bPat =
        ((((uint32_t)((lane & 7) + ((lane & 16) >> 1)) * 68u) +
          ((lane & 8) >> 1)) << 2);
    const uint32_t sKa = smem_u32(sK) + bPat;
    const uint32_t sVha = smem_u32(sVh) + bPat;
    const uint32_t R16 = (16 * 68) << 2;

    float o[8][4];
#pragma unroll
    for (int j = 0; j < 8; j++)
#pragma unroll
        for (int r = 0; r < 4; r++) o[j][r] = 0.f;
    float m0 = -1e30f, m1 = -1e30f, sum0 = 0.f, sum1 = 0.f;

    for (int jb = 0; jb < 16; jb++) {
        __syncthreads();
#pragma unroll
        for (int it = 0; it < 4; it++) {
            int f = tid + it * 256;
            int key = f >> 4;
            int d4 = (f & 15) << 2;
            float4 v = *(const float4*)(kb + (long)(jb * 64 + key) * D_ + d4);
            *(uint4*)(sK + key * 68 + d4) = hi4(v);
        }
#pragma unroll
        for (int it = 0; it < 4; it++) {
            int f = tid + it * 256;
            int key = f >> 4;
            int d4 = (f & 15) << 2;
            float4 v = *(const float4*)(vb + (long)(jb * 64 + key) * D_ + d4);
            float vv[4] = {v.x, v.y, v.z, v.w};
#pragma unroll
            for (int i = 0; i < 4; i++)
                *(uint32_t*)(sVh + (d4 + i) * 68 + key) = f2tf32(vv[i]);
        }
        __syncthreads();

        // S = Q K^T
        float accS[8][4];
#pragma unroll
        for (int j = 0; j < 8; j++)
#pragma unroll
            for (int r = 0; r < 4; r++) accS[j][r] = 0.f;
#pragma unroll
        for (int s = 0; s < 8; s++) {
            const uint32_t ks = (uint32_t)s * 32;
            uint32_t af[4], bf[16];
            ldsm4(af, sQa + ks);
            ldsm4(bf + 0,  sKa + ks);
            ldsm4(bf + 4,  sKa + ks + R16);
            ldsm4(bf + 8,  sKa + ks + 2 * R16);
            ldsm4(bf + 12, sKa + ks + 3 * R16);
#pragma unroll
            for (int j = 0; j < 8; j++) mma8(accS[j], af, bf + 2 * j);
        }

        // add E, scale by 1/16
#pragma unroll
        for (int j = 0; j < 8; j++) {
            const int col = jb * 64 + 8 * j + 2 * t;
            float2 ea = *(const float2*)(e0 + col);
            float2 ebv = *(const float2*)(e1 + col);
            accS[j][0] = (accS[j][0] + ea.x) * 0.0625f;
            accS[j][1] = (accS[j][1] + ea.y) * 0.0625f;
            accS[j][2] = (accS[j][2] + ebv.x) * 0.0625f;
            accS[j][3] = (accS[j][3] + ebv.y) * 0.0625f;
        }

        // online softmax
        float mx0 = -1e30f, mx1 = -1e30f;
#pragma unroll
        for (int j = 0; j < 8; j++) {
            mx0 = fmaxf(mx0, fmaxf(accS[j][0], accS[j][1]));
            mx1 = fmaxf(mx1, fmaxf(accS[j][2], accS[j][3]));
        }
#pragma unroll
        for (int off = 1; off <= 2; off <<= 1) {
            mx0 = fmaxf(mx0, __shfl_xor_sync(0xffffffffu, mx0, off));
            mx1 = fmaxf(mx1, __shfl_xor_sync(0xffffffffu, mx1, off));
        }
        const float nm0 = fmaxf(m0, mx0), nm1 = fmaxf(m1, mx1);
        const float sc0 = __expf(m0 - nm0), sc1 = __expf(m1 - nm1);
        float rs0 = 0.f, rs1 = 0.f;
#pragma unroll
        for (int j = 0; j < 8; j++) {
            accS[j][0] = __expf(accS[j][0] - nm0);
            accS[j][1] = __expf(accS[j][1] - nm0);
            accS[j][2] = __expf(accS[j][2] - nm1);
            accS[j][3] = __expf(accS[j][3] - nm1);
            rs0 += accS[j][0] + accS[j][1];
            rs1 += accS[j][2] + accS[j][3];
        }
#pragma unroll
        for (int off = 1; off <= 2; off <<= 1) {
            rs0 += __shfl_xor_sync(0xffffffffu, rs0, off);
            rs1 += __shfl_xor_sync(0xffffffffu, rs1, off);
        }
        sum0 = sum0 * sc0 + rs0;
        sum1 = sum1 * sc1 + rs1;
        m0 = nm0; m1 = nm1;
#pragma unroll
        for (int j = 0; j < 8; j++) {
            o[j][0] *= sc0; o[j][1] *= sc0;
            o[j][2] *= sc1; o[j][3] *= sc1;
        }

        // O += P V (1-term; acc-layout -> A-layout via quad shuffles)
        const int sl0 = (lane & ~3) | (t >> 1);
        const int sl2 = sl0 + 2;
#pragma unroll
        for (int kt = 0; kt < 8; kt++) {
            float p00 = __shfl_sync(0xffffffffu, accS[kt][0], sl0);
            float p01 = __shfl_sync(0xffffffffu, accS[kt][1], sl0);
            float p20 = __shfl_sync(0xffffffffu, accS[kt][0], sl2);
            float p21 = __shfl_sync(0xffffffffu, accS[kt][1], sl2);
            float p10 = __shfl_sync(0xffffffffu, accS[kt][2], sl0);
            float p11 = __shfl_sync(0xffffffffu, accS[kt][3], sl0);
            float p30 = __shfl_sync(0xffffffffu, accS[kt][2], sl2);
            float p31 = __shfl_sync(0xffffffffu, accS[kt][3], sl2);
            float a0 = (t & 1) ? p01 : p00;
            float a1 = (t & 1) ? p11 : p10;
            float a2 = (t & 1) ? p21 : p20;
            float a3 = (t & 1) ? p31 : p30;
            uint32_t ah[4];
            ah[0] = f2tf32(a0); ah[1] = f2tf32(a1);
            ah[2] = f2tf32(a2); ah[3] = f2tf32(a3);

            const uint32_t ks = (uint32_t)kt * 32;
            uint32_t bv[16];
            ldsm4(bv + 0,  sVha + ks);
            ldsm4(bv + 4,  sVha + ks + R16);
            ldsm4(bv + 8,  sVha + ks + 2 * R16);
            ldsm4(bv + 12, sVha + ks + 3 * R16);
#pragma unroll
            for (int j = 0; j < 8; j++)
                mma8(o[j], ah, bv + 2 * j);
        }
    }

    const float inv0 = 1.f / sum0, inv1 = 1.f / sum1;
    float* ob = O + ((long)b * L_ + l0 + w * 16) * D_ + h * 64;
#pragma unroll
    for (int j = 0; j < 8; j++) {
        const int col = 8 * j + 2 * t;
        *(float2*)(ob + (long)g * D_ + col) =
            make_float2(o[j][0] * inv0, o[j][1] * inv0);
        *(float2*)(ob + (long)(g + 8) * D_ + col) =
            make_float2(o[j][2] * inv1, o[j][3] * inv1);
    }
}

// ---------------------------------------------------------------------------
extern "C" void kernel_launch(void* const* d_in, const int* in_sizes, int n_in,
                              void* d_out, int out_size)
{
    const float* query = (const float*)d_in[0];
    const float* key   = (const float*)d_in[1];
    const float* value = (const float*)d_in[2];
    const float* news  = (const float*)d_in[3];
    const float* Wq = (const float*)d_in[4];
    const float* bq = (const float*)d_in[5];
    const float* Wk = (const float*)d_in[6];
    const float* bk = (const float*)d_in[7];
    const float* Wv = (const float*)d_in[8];
    const float* bv = (const float*)d_in[9];
    const float* Wn = (const float*)d_in[10];
    const float* bn = (const float*)d_in[11];
    const float* Wo = (const float*)d_in[12];
    const float* bo = (const float*)d_in[13];
    // d_in[14] = pos. Mathematically irrelevant (swapaxes of swapped enh == enh).

    float *pq, *pk, *pv, *pn, *pnkT, *pG, *pT, *penh, *patt;
    cudaGetSymbolAddress((void**)&pq,   g_q);
    cudaGetSymbolAddress((void**)&pk,   g_k);
    cudaGetSymbolAddress((void**)&pv,   g_v);
    cudaGetSymbolAddress((void**)&pn,   g_n);
    cudaGetSymbolAddress((void**)&pnkT, g_nkT);
    cudaGetSymbolAddress((void**)&pG,   g_G);
    cudaGetSymbolAddress((void**)&pT,   g_T);
    cudaGetSymbolAddress((void**)&penh, g_enh);
    cudaGetSymbolAddress((void**)&patt, g_att);

    const int M = B_ * L_;  // 8192
    dim3 blk(256);
    const int smem4 = 2 * 4 * 4608 * 4;  // 147456
    const int smem2 = 2 * 3 * 4608 * 4;  // 110592
    cudaFuncSetAttribute(tc_proj,    cudaFuncAttributeMaxDynamicSharedMemorySize, smem4);
    cudaFuncSetAttribute(tc_gemm<3>, cudaFuncAttributeMaxDynamicSharedMemorySize, smem4);
    cudaFuncSetAttribute(tc_gemm<2>, cudaFuncAttributeMaxDynamicSharedMemorySize, smem2);

    // all 4 projections in one launch (z: 0=q, 1=k, 2=nk, 3=v[2-term])
    ProjArgs pa;
    pa.in[0] = query; pa.in[1] = key; pa.in[2] = news; pa.in[3] = value;
    pa.W[0] = Wq; pa.W[1] = Wk; pa.W[2] = Wn; pa.W[3] = Wv;
    pa.bias[0] = bq; pa.bias[1] = bk; pa.bias[2] = bn; pa.bias[3] = bv;
    pa.out[0] = pq; pa.out[1] = pk; pa.out[2] = pn; pa.out[3] = pv;
    tc_proj<<<dim3(D_ / 128, M / 128, 4), blk, smem4>>>(pa);

    // enh = q (nk^T nk) k^T, restructured:
    transpose_ld<<<dim3(D_ / 32, L_ / 32, B_), dim3(32, 8)>>>(pn, pnkT);
    tc_gemm<3><<<dim3(D_ / 128, D_ / 128, B_), blk, smem4>>>(pnkT, pnkT, pG, nullptr,
        D_, D_, L_, (long)D_ * L_, (long)D_ * L_, (long)D_ * D_);
    tc_gemm<3><<<dim3(D_ / 128, L_ / 128, B_), blk, smem4>>>(pq, pG, pT, nullptr,
        L_, D_, D_, (long)L_ * D_, (long)D_ * D_, (long)L_ * D_);
    tc_gemm<3><<<dim3(L_ / 128, L_ / 128, B_), blk, smem4>>>(pT, pk, penh, nullptr,
        L_, L_, D_, (long)L_ * D_, (long)L_ * D_, (long)L_ * L_);

    // fused attention
    const int attn_smem = (128 * 68 + 2 * 64 * 68) * 4;  // 69632
    cudaFuncSetAttribute(attn_mma, cudaFuncAttributeMaxDynamicSharedMemorySize,
                         attn_smem);
    attn_mma<<<dim3(L_ / 128, B_ * H_), blk, attn_smem>>>(pq, pk, pv, penh, patt);

    // output projection (2-term) -> d_out
    tc_gemm<2><<<dim3(D_ / 128, M / 128, 1), blk, smem2>>>(patt, Wo, (float*)d_out, bo,
                                                           M, D_, D_, 0, 0, 0);
}